// round 3
// baseline (speedup 1.0000x reference)
#include <cuda_runtime.h>
#include <math.h>

#define SS 64
#define WW 128
#define DD 256
#define HWW 256
#define NC 13

// ---------------- scratch ----------------
__device__ float g_gi[2 * WW * SS * 768];      // [d][w][s][768]
__device__ float g_h[2][2 * SS * HWW];         // ping-pong [buf][d][s][k]
__device__ float g_wordenc[SS * WW * 512];     // [s*128+w][512]
__device__ float g_sentsumm[SS * 512];         // [s][512]
__device__ float g_gis[2 * SS * 1536];         // [d][s][1536]
__device__ float g_sentenc[SS * 1024];         // [s][1024]
__device__ float g_usent[SS * 1024];           // [s][1024]
__device__ float g_doc[1024];
__device__ unsigned g_bar_cnt = 0;
__device__ unsigned g_bar_gen = 0;

__device__ __forceinline__ float fsig(float x) { return 1.0f / (1.0f + expf(-x)); }

// ---------------- init ----------------
__global__ void k_init(float* __restrict__ out) {
    int i = blockIdx.x * blockDim.x + threadIdx.x;          // grid 128x256 = 32768
    if (i < 8256) out[i] = 1.0f;                            // word_w + sent_w are all ones
    if (i < 2 * SS * HWW) g_h[0][i] = 0.0f;                 // h0 = 0
    if (i < SS * 512) g_sentsumm[i] = 0.0f;                 // atomic target
}

// ---------------- K1: gi[d][w][s][n] = emb[doc[s][w]] @ wWi[d]^T + wbi[d] ----------------
// grid (12 ntile, 128 w, 2 d), block 256. Tile 64(s) x 64(n), K=256.
__global__ void __launch_bounds__(256) k_gi(const int* __restrict__ doc,
                                            const float* __restrict__ emb,
                                            const float* __restrict__ wWi,
                                            const float* __restrict__ wbi) {
    int n0 = blockIdx.x * 64, w = blockIdx.y, d = blockIdx.z;
    __shared__ int toks[64];
    __shared__ float As[32 * 68];
    __shared__ float Bs[32 * 68];
    int tid = threadIdx.x;
    if (tid < 64) toks[tid] = doc[tid * WW + w];
    __syncthreads();
    int tx = tid & 15, ty = tid >> 4;
    float acc[4][4] = {};
    for (int kc = 0; kc < 256; kc += 32) {
        for (int e = tid; e < 2048; e += 256) {
            int row = e >> 5, kk = e & 31;
            As[kk * 68 + row] = emb[(long)toks[row] * DD + kc + kk];
            Bs[kk * 68 + row] = wWi[(d * 768 + n0 + row) * 256 + kc + kk];
        }
        __syncthreads();
#pragma unroll
        for (int kk = 0; kk < 32; kk++) {
            float4 a = *(const float4*)&As[kk * 68 + ty * 4];
            float4 b = *(const float4*)&Bs[kk * 68 + tx * 4];
            float av[4] = {a.x, a.y, a.z, a.w};
            float bv[4] = {b.x, b.y, b.z, b.w};
#pragma unroll
            for (int i = 0; i < 4; i++)
#pragma unroll
                for (int j = 0; j < 4; j++) acc[i][j] += av[i] * bv[j];
        }
        __syncthreads();
    }
    float4 bv = *(const float4*)&wbi[d * 768 + n0 + tx * 4];
#pragma unroll
    for (int i = 0; i < 4; i++) {
        int s = ty * 4 + i;
        float4 v = make_float4(acc[i][0] + bv.x, acc[i][1] + bv.y,
                               acc[i][2] + bv.z, acc[i][3] + bv.w);
        *(float4*)&g_gi[((d * WW + w) * SS + s) * 768 + n0 + tx * 4] = v;
    }
}

// ---------------- grid barrier (all 128 CTAs resident) ----------------
__device__ __forceinline__ void gridbar(unsigned nb) {
    __syncthreads();
    if (threadIdx.x == 0) {
        unsigned gen = *(volatile unsigned*)&g_bar_gen;
        __threadfence();
        if (atomicAdd(&g_bar_cnt, 1u) == nb - 1u) {
            g_bar_cnt = 0;
            __threadfence();
            atomicAdd(&g_bar_gen, 1u);
        } else {
            while (*(volatile unsigned*)&g_bar_gen == gen) {}
        }
        __threadfence();
    }
    __syncthreads();
}

// ---------------- K2: persistent word-GRU recurrence ----------------
// 128 CTAs = d(2) x sb(8: 8 sent each) x jb(8: 32 j each). 256 thr = 8 ks-slices x 32 j.
__global__ void __launch_bounds__(256, 1) k_recur(const float* __restrict__ wWh,
                                                  const float* __restrict__ wbh) {
    __shared__ float h_sm[2048];          // [s_loc][k]
    __shared__ float red_sm[32 * 201];    // [j_loc][g*8+s][ks], stride 201 (bank-safe)
    int c = blockIdx.x;
    int d = c >> 6, sb = (c >> 3) & 7, jb = c & 7;
    int tid = threadIdx.x;
    int ks = tid >> 5, lane = tid & 31;   // compute-phase identity
    int sb8 = sb * 8;

    // Wh slice in registers: rows (g,jb*32+lane), cols ks*32..+31  (96 floats)
    float whr[3][32];
#pragma unroll
    for (int g = 0; g < 3; g++) {
        const float* wr = wWh + (d * 768 + g * 256 + jb * 32 + lane) * 256 + ks * 32;
#pragma unroll
        for (int kk = 0; kk < 32; kk++) whr[g][kk] = wr[kk];
    }
    // phase-2 identity + per-thread constants
    int s2 = tid >> 5, j2 = tid & 31;
    int jg2 = jb * 32 + j2;
    float bhr = wbh[d * 768 + jg2];
    float bhz = wbh[d * 768 + 256 + jg2];
    float bhn = wbh[d * 768 + 512 + jg2];

    int p = 0;
    for (int w = 0; w < WW; w++) {
        // load h_old (8 sentences x 256 k, contiguous) into smem
        {
            const float4* src = (const float4*)(g_h[p] + d * (SS * HWW) + sb8 * HWW);
            float4* dst = (float4*)h_sm;
            dst[tid] = src[tid];
            dst[tid + 256] = src[tid + 256];
        }
        __syncthreads();
        // gh partials: acc[g][s] over k in [ks*32, ks*32+32)
        float acc[3][8] = {};
#pragma unroll
        for (int kk = 0; kk < 32; kk++) {
            int k = ks * 32 + kk;
#pragma unroll
            for (int s = 0; s < 8; s++) {
                float hv = h_sm[s * 256 + k];     // warp-uniform -> broadcast
                acc[0][s] += hv * whr[0][kk];
                acc[1][s] += hv * whr[1][kk];
                acc[2][s] += hv * whr[2][kk];
            }
        }
        // store partials
#pragma unroll
        for (int g = 0; g < 3; g++)
#pragma unroll
            for (int s = 0; s < 8; s++)
                red_sm[lane * 201 + (g * 8 + s) * 8 + ks] = acc[g][s];
        __syncthreads();
        // phase 2: thread (s2, j2) reduces 8 slices per gate, applies GRU cell
        float gh[3];
#pragma unroll
        for (int g = 0; g < 3; g++) {
            float v = 0.f;
#pragma unroll
            for (int q = 0; q < 8; q++) v += red_sm[j2 * 201 + (g * 8 + s2) * 8 + q];
            gh[g] = v;
        }
        int sg = sb8 + s2;
        const float* gi = g_gi + ((d * WW + w) * SS + sg) * 768 + jg2;
        float h_old = h_sm[s2 * 256 + jg2];
        float r = fsig(gi[0] + gh[0] + bhr);
        float z = fsig(gi[256] + gh[1] + bhz);
        float n = tanhf(gi[512] + r * (gh[2] + bhn));
        float hn = (1.0f - z) * n + z * h_old;
        g_h[p ^ 1][d * (SS * HWW) + sg * HWW + jg2] = hn;
        g_wordenc[(sg * WW + w) * 512 + d * 256 + jg2] = hn;
        gridbar(gridDim.x);
        p ^= 1;
    }
}

// ---------------- K3: u_word = tanh(wordenc @ waW^T + wab); sent_summ += sum over w ----------------
// grid (8 ntile, 128 mtile). Each 64-row tile lies inside one sentence (128 w per s).
__global__ void __launch_bounds__(256) k_uword(const float* __restrict__ waW,
                                               const float* __restrict__ wab) {
    int n0 = blockIdx.x * 64, mt = blockIdx.y;
    __shared__ float As[32 * 68];
    __shared__ float Bs[32 * 68];
    __shared__ float red2[16 * 64];
    int tid = threadIdx.x, tx = tid & 15, ty = tid >> 4;
    float acc[4][4] = {};
    for (int kc = 0; kc < 512; kc += 32) {
        for (int e = tid; e < 2048; e += 256) {
            int row = e >> 5, kk = e & 31;
            As[kk * 68 + row] = g_wordenc[(mt * 64 + row) * 512 + kc + kk];
            Bs[kk * 68 + row] = waW[(n0 + row) * 512 + kc + kk];
        }
        __syncthreads();
#pragma unroll
        for (int kk = 0; kk < 32; kk++) {
            float4 a = *(const float4*)&As[kk * 68 + ty * 4];
            float4 b = *(const float4*)&Bs[kk * 68 + tx * 4];
            float av[4] = {a.x, a.y, a.z, a.w};
            float bv[4] = {b.x, b.y, b.z, b.w};
#pragma unroll
            for (int i = 0; i < 4; i++)
#pragma unroll
                for (int j = 0; j < 4; j++) acc[i][j] += av[i] * bv[j];
        }
        __syncthreads();
    }
    float4 bb = *(const float4*)&wab[n0 + tx * 4];
    float bv[4] = {bb.x, bb.y, bb.z, bb.w};
    float cs[4] = {};
#pragma unroll
    for (int i = 0; i < 4; i++)
#pragma unroll
        for (int j = 0; j < 4; j++) cs[j] += tanhf(acc[i][j] + bv[j]);
#pragma unroll
    for (int j = 0; j < 4; j++) red2[ty * 64 + tx * 4 + j] = cs[j];
    __syncthreads();
    if (tid < 64) {
        float v = 0.f;
#pragma unroll
        for (int q = 0; q < 16; q++) v += red2[q * 64 + tid];
        int s = mt >> 1;
        atomicAdd(&g_sentsumm[s * 512 + n0 + tid], v);
    }
}

// ---------------- K4: sentence gi[d][s][n] = sent_summ @ sWi[d]^T + sbi[d] ----------------
// grid (24 ntile, 2 d). M=64 (single tile), K=512.
__global__ void __launch_bounds__(256) k_sgi(const float* __restrict__ sWi,
                                             const float* __restrict__ sbi) {
    int n0 = blockIdx.x * 64, d = blockIdx.y;
    __shared__ float As[32 * 68];
    __shared__ float Bs[32 * 68];
    int tid = threadIdx.x, tx = tid & 15, ty = tid >> 4;
    float acc[4][4] = {};
    for (int kc = 0; kc < 512; kc += 32) {
        for (int e = tid; e < 2048; e += 256) {
            int row = e >> 5, kk = e & 31;
            As[kk * 68 + row] = g_sentsumm[row * 512 + kc + kk];
            Bs[kk * 68 + row] = sWi[(d * 1536 + n0 + row) * 512 + kc + kk];
        }
        __syncthreads();
#pragma unroll
        for (int kk = 0; kk < 32; kk++) {
            float4 a = *(const float4*)&As[kk * 68 + ty * 4];
            float4 b = *(const float4*)&Bs[kk * 68 + tx * 4];
            float av[4] = {a.x, a.y, a.z, a.w};
            float bv[4] = {b.x, b.y, b.z, b.w};
#pragma unroll
            for (int i = 0; i < 4; i++)
#pragma unroll
                for (int j = 0; j < 4; j++) acc[i][j] += av[i] * bv[j];
        }
        __syncthreads();
    }
    float4 bb = *(const float4*)&sbi[d * 1536 + n0 + tx * 4];
    float bvv[4] = {bb.x, bb.y, bb.z, bb.w};
#pragma unroll
    for (int i = 0; i < 4; i++) {
        int s = ty * 4 + i;
        float4 v = make_float4(acc[i][0] + bvv[0], acc[i][1] + bvv[1],
                               acc[i][2] + bvv[2], acc[i][3] + bvv[3]);
        *(float4*)&g_gis[(d * SS + s) * 1536 + n0 + tx * 4] = v;
    }
}

// ---------------- K5: sentence GRU-cell gates (zero state) ----------------
__global__ void k_sgates(const float* __restrict__ sbh) {
    int idx = blockIdx.x * blockDim.x + threadIdx.x;   // 65536
    int d = idx >> 15, r = idx & 32767, s = r >> 9, j = r & 511;
    const float* gi = g_gis + (d * SS + s) * 1536;
    float hr = sbh[d * 1536 + j], hz = sbh[d * 1536 + 512 + j], hn = sbh[d * 1536 + 1024 + j];
    float rr = fsig(gi[j] + hr);
    float z = fsig(gi[j + 512] + hz);
    float n = tanhf(gi[j + 1024] + rr * hn);
    g_sentenc[s * 1024 + d * 512 + j] = (1.0f - z) * n;
}

// ---------------- K6: u_sent = tanh(sentenc @ saW^T + sab) ----------------
// grid 16 ntiles. M=64, K=1024.
__global__ void __launch_bounds__(256) k_usent(const float* __restrict__ saW,
                                               const float* __restrict__ sab) {
    int n0 = blockIdx.x * 64;
    __shared__ float As[32 * 68];
    __shared__ float Bs[32 * 68];
    int tid = threadIdx.x, tx = tid & 15, ty = tid >> 4;
    float acc[4][4] = {};
    for (int kc = 0; kc < 1024; kc += 32) {
        for (int e = tid; e < 2048; e += 256) {
            int row = e >> 5, kk = e & 31;
            As[kk * 68 + row] = g_sentenc[row * 1024 + kc + kk];
            Bs[kk * 68 + row] = saW[(n0 + row) * 1024 + kc + kk];
        }
        __syncthreads();
#pragma unroll
        for (int kk = 0; kk < 32; kk++) {
            float4 a = *(const float4*)&As[kk * 68 + ty * 4];
            float4 b = *(const float4*)&Bs[kk * 68 + tx * 4];
            float av[4] = {a.x, a.y, a.z, a.w};
            float bv[4] = {b.x, b.y, b.z, b.w};
#pragma unroll
            for (int i = 0; i < 4; i++)
#pragma unroll
                for (int j = 0; j < 4; j++) acc[i][j] += av[i] * bv[j];
        }
        __syncthreads();
    }
    float4 bb = *(const float4*)&sab[n0 + tx * 4];
    float bvv[4] = {bb.x, bb.y, bb.z, bb.w};
#pragma unroll
    for (int i = 0; i < 4; i++) {
        int s = ty * 4 + i;
#pragma unroll
        for (int j = 0; j < 4; j++)
            g_usent[s * 1024 + n0 + tx * 4 + j] = tanhf(acc[i][j] + bvv[j]);
    }
}

// ---------------- K7: doc[n] = sum_s u_sent[s][n] ----------------
__global__ void k_docsum() {
    int n = blockIdx.x * blockDim.x + threadIdx.x;   // 1024
    float v = 0.f;
#pragma unroll 8
    for (int s = 0; s < SS; s++) v += g_usent[s * 1024 + n];
    g_doc[n] = v;
}

// ---------------- K8: logits + log_softmax ----------------
__global__ void k_final(const float* __restrict__ doW, const float* __restrict__ dob,
                        float* __restrict__ out) {
    __shared__ float lg[16];
    int warp = threadIdx.x >> 5, lane = threadIdx.x & 31;
    for (int c = warp; c < NC; c += 8) {
        float v = 0.f;
        for (int n = lane; n < 1024; n += 32) v += g_doc[n] * doW[c * 1024 + n];
#pragma unroll
        for (int o = 16; o; o >>= 1) v += __shfl_xor_sync(0xffffffff, v, o);
        if (lane == 0) lg[c] = v + dob[c];
    }
    __syncthreads();
    if (threadIdx.x == 0) {
        float mx = -1e30f;
        for (int c = 0; c < NC; c++) mx = fmaxf(mx, lg[c]);
        float se = 0.f;
        for (int c = 0; c < NC; c++) se += expf(lg[c] - mx);
        float lse = mx + logf(se);
        for (int c = 0; c < NC; c++) out[8256 + c] = lg[c] - lse;
    }
}

extern "C" void kernel_launch(void* const* d_in, const int* in_sizes, int n_in,
                              void* d_out, int out_size) {
    const int*   doc = (const int*)d_in[0];
    const float* emb = (const float*)d_in[1];
    const float* wWi = (const float*)d_in[2];
    const float* wWh = (const float*)d_in[3];
    const float* wbi = (const float*)d_in[4];
    const float* wbh = (const float*)d_in[5];
    const float* sWi = (const float*)d_in[6];
    // d_in[7] = s_Wh (dead: multiplied by zero state)
    const float* sbi = (const float*)d_in[8];
    const float* sbh = (const float*)d_in[9];
    const float* waW = (const float*)d_in[10];
    const float* wab = (const float*)d_in[11];
    // d_in[12] = uw_W (dead: softmax over size-1 axis)
    const float* saW = (const float*)d_in[13];
    const float* sab = (const float*)d_in[14];
    // d_in[15] = us_W (dead)
    const float* doW = (const float*)d_in[16];
    const float* dob = (const float*)d_in[17];
    float* out = (float*)d_out;

    k_init<<<128, 256>>>(out);
    k_gi<<<dim3(12, 128, 2), 256>>>(doc, emb, wWi, wbi);
    k_recur<<<128, 256>>>(wWh, wbh);
    k_uword<<<dim3(8, 128), 256>>>(waW, wab);
    k_sgi<<<dim3(24, 2), 256>>>(sWi, sbi);
    k_sgates<<<256, 256>>>(sbh);
    k_usent<<<16, 256>>>(saW, sab);
    k_docsum<<<4, 256>>>();
    k_final<<<1, 256>>>(doW, dob, out);
}

// round 4
// speedup vs baseline: 1.0720x; 1.0720x over previous
#include <cuda_runtime.h>
#include <math.h>

#define SS 64
#define WW 128
#define DD 256
#define HWW 256
#define NC 13

// ---------------- scratch ----------------
__device__ float g_gi[2 * WW * SS * 768];      // [d][w][s][768]
__device__ float g_wordenc[SS * WW * 512];     // [s*128+w][512]
__device__ float g_sentsumm[SS * 512];         // [s][512]
__device__ float g_gis[2 * SS * 1536];         // [d][s][1536]
__device__ float g_sentenc[SS * 1024];         // [s][1024]
__device__ float g_usent[SS * 1024];           // [s][1024]
__device__ float g_doc[1024];

__device__ __forceinline__ float fsig(float x) { return 1.0f / (1.0f + expf(-x)); }

__device__ __forceinline__ unsigned long long ffma2(unsigned long long a,
                                                    unsigned long long b,
                                                    unsigned long long c) {
    unsigned long long d;
    asm("fma.rn.f32x2 %0, %1, %2, %3;" : "=l"(d) : "l"(a), "l"(b), "l"(c));
    return d;
}

__device__ __forceinline__ unsigned smem_u32(const void* p) {
    unsigned a;
    asm("{ .reg .u64 t; cvta.to.shared.u64 t, %1; cvt.u32.u64 %0, t; }" : "=r"(a) : "l"(p));
    return a;
}

// ---------------- init ----------------
__global__ void k_init(float* __restrict__ out) {
    int i = blockIdx.x * blockDim.x + threadIdx.x;          // 128x256 = 32768
    if (i < 8256) out[i] = 1.0f;                            // word_w + sent_w are all ones
    if (i < SS * 512) g_sentsumm[i] = 0.0f;                 // atomic target
}

// ---------------- K1: gi[d][w][s][n] = emb[doc[s][w]] @ wWi[d]^T + wbi[d] ----------------
__global__ void __launch_bounds__(256) k_gi(const int* __restrict__ doc,
                                            const float* __restrict__ emb,
                                            const float* __restrict__ wWi,
                                            const float* __restrict__ wbi) {
    int n0 = blockIdx.x * 64, w = blockIdx.y, d = blockIdx.z;
    __shared__ int toks[64];
    __shared__ float As[32 * 68];
    __shared__ float Bs[32 * 68];
    int tid = threadIdx.x;
    if (tid < 64) toks[tid] = doc[tid * WW + w];
    __syncthreads();
    int tx = tid & 15, ty = tid >> 4;
    float acc[4][4] = {};
    for (int kc = 0; kc < 256; kc += 32) {
        for (int e = tid; e < 2048; e += 256) {
            int row = e >> 5, kk = e & 31;
            As[kk * 68 + row] = emb[(long)toks[row] * DD + kc + kk];
            Bs[kk * 68 + row] = wWi[(d * 768 + n0 + row) * 256 + kc + kk];
        }
        __syncthreads();
#pragma unroll
        for (int kk = 0; kk < 32; kk++) {
            float4 a = *(const float4*)&As[kk * 68 + ty * 4];
            float4 b = *(const float4*)&Bs[kk * 68 + tx * 4];
            float av[4] = {a.x, a.y, a.z, a.w};
            float bv[4] = {b.x, b.y, b.z, b.w};
#pragma unroll
            for (int i = 0; i < 4; i++)
#pragma unroll
                for (int j = 0; j < 4; j++) acc[i][j] += av[i] * bv[j];
        }
        __syncthreads();
    }
    float4 bv = *(const float4*)&wbi[d * 768 + n0 + tx * 4];
#pragma unroll
    for (int i = 0; i < 4; i++) {
        int s = ty * 4 + i;
        float4 v = make_float4(acc[i][0] + bv.x, acc[i][1] + bv.y,
                               acc[i][2] + bv.z, acc[i][3] + bv.w);
        *(float4*)&g_gi[((d * WW + w) * SS + s) * 768 + n0 + tx * 4] = v;
    }
}

// ---------------- K2: persistent word-GRU recurrence (clusters of 8, DSMEM h exchange) ----
// 128 CTAs = 16 clusters. Cluster = the 8 jb-splits of one (d, sb).
// blockIdx.x = (d*8+sb)*8 + jb  ->  cluster rank = jb.
// 256 thr: phase1 (ks = tid>>5 k-slice, lane = j within slice), phase2 (s2 = tid>>5, j2 = tid&31).
__global__ void __launch_bounds__(256, 1) __cluster_dims__(8, 1, 1)
k_recur(const float* __restrict__ wWh, const float* __restrict__ wbh) {
    __shared__ float h_sm[2][2048];        // ping-pong [buf][s_loc*256 + j]
    __shared__ float red_sm[32 * 201];     // [j_loc][(g*8+s)*8 + ks]
    int c = blockIdx.x;
    int d = c >> 6, sb = (c >> 3) & 7, jb = c & 7;
    int tid = threadIdx.x;
    int ks = tid >> 5, lane = tid & 31;
    int sb8 = sb * 8;

    // Wh slice in registers, packed as k-pairs: rows (g, jb*32+lane), cols ks*32..+31
    unsigned long long whr2[3][16];
#pragma unroll
    for (int g = 0; g < 3; g++) {
        const unsigned long long* wr = (const unsigned long long*)
            (wWh + (d * 768 + g * 256 + jb * 32 + lane) * 256 + ks * 32);
#pragma unroll
        for (int t = 0; t < 16; t++) whr2[g][t] = wr[t];
    }

    // phase-2 identity + constants
    int s2 = tid >> 5, j2 = tid & 31;
    int jg2 = jb * 32 + j2;
    float bhr = wbh[d * 768 + jg2];
    float bhz = wbh[d * 768 + 256 + jg2];
    float bhn = wbh[d * 768 + 512 + jg2];

    // zero own h0 buffer
#pragma unroll
    for (int q = 0; q < 8; q++) h_sm[0][tid * 8 + q] = 0.0f;

    // precompute DSMEM peer addresses for this thread's h element
    unsigned my_base = smem_u32(&h_sm[0][0]);
    unsigned elem_off = (unsigned)(s2 * 256 + jg2) * 4u;
    unsigned pa[8];
#pragma unroll
    for (int r = 0; r < 8; r++) {
        unsigned peer;
        asm("mapa.shared::cluster.u32 %0, %1, %2;" : "=r"(peer) : "r"(my_base), "r"(r));
        pa[r] = peer + elem_off;
    }
    __syncthreads();

    int p = 0;
    for (int w = 0; w < WW; w++) {
        // prefetch gi (independent of h)
        const float* gi = g_gi + ((d * WW + w) * SS + (sb8 + s2)) * 768 + jg2;
        float gi0 = __ldg(gi);
        float gi1 = __ldg(gi + 256);
        float gi2 = __ldg(gi + 512);

        // phase 1: gh partials over k-slice [ks*32, ks*32+32), packed f32x2 along k
        const float* hb = &h_sm[p][ks * 32];
        unsigned long long acc2[3][8];
#pragma unroll
        for (int g = 0; g < 3; g++)
#pragma unroll
            for (int s = 0; s < 8; s++) acc2[g][s] = 0ull;
#pragma unroll
        for (int kk4 = 0; kk4 < 8; kk4++) {
#pragma unroll
            for (int s = 0; s < 8; s++) {
                ulonglong2 hv = *(const ulonglong2*)(hb + s * 256 + kk4 * 4);
#pragma unroll
                for (int g = 0; g < 3; g++) {
                    acc2[g][s] = ffma2(hv.x, whr2[g][kk4 * 2], acc2[g][s]);
                    acc2[g][s] = ffma2(hv.y, whr2[g][kk4 * 2 + 1], acc2[g][s]);
                }
            }
        }
#pragma unroll
        for (int g = 0; g < 3; g++)
#pragma unroll
            for (int s = 0; s < 8; s++) {
                float2 f = *(float2*)&acc2[g][s];
                red_sm[lane * 201 + (g * 8 + s) * 8 + ks] = f.x + f.y;
            }
        __syncthreads();

        // phase 2: reduce 8 slices, apply GRU cell
        float gh[3];
#pragma unroll
        for (int g = 0; g < 3; g++) {
            float v = 0.f;
#pragma unroll
            for (int q = 0; q < 8; q++) v += red_sm[j2 * 201 + (g * 8 + s2) * 8 + q];
            gh[g] = v;
        }
        float h_old = h_sm[p][s2 * 256 + jg2];
        float r = fsig(gi0 + gh[0] + bhr);
        float z = fsig(gi1 + gh[1] + bhz);
        float n = tanhf(gi2 + r * (gh[2] + bhn));
        float hn = (1.0f - z) * n + z * h_old;

        // broadcast new h element to all 8 cluster CTAs' smem (buffer p^1)
        unsigned poff = (unsigned)((p ^ 1) * 8192);
#pragma unroll
        for (int r8 = 0; r8 < 8; r8++)
            asm volatile("st.shared::cluster.f32 [%0], %1;" :: "r"(pa[r8] + poff), "f"(hn));
        g_wordenc[((sb8 + s2) * WW + w) * 512 + d * 256 + jg2] = hn;

        // cluster barrier: release our DSMEM stores, acquire peers'
        asm volatile("barrier.cluster.arrive.aligned;" ::: "memory");
        asm volatile("barrier.cluster.wait.aligned;" ::: "memory");
        p ^= 1;
    }
}

// ---------------- K3: u_word = tanh(wordenc @ waW^T + wab); sent_summ += sum over w ------
__global__ void __launch_bounds__(256) k_uword(const float* __restrict__ waW,
                                               const float* __restrict__ wab) {
    int n0 = blockIdx.x * 64, mt = blockIdx.y;
    __shared__ float As[32 * 68];
    __shared__ float Bs[32 * 68];
    __shared__ float red2[16 * 64];
    int tid = threadIdx.x, tx = tid & 15, ty = tid >> 4;
    float acc[4][4] = {};
    for (int kc = 0; kc < 512; kc += 32) {
        for (int e = tid; e < 2048; e += 256) {
            int row = e >> 5, kk = e & 31;
            As[kk * 68 + row] = g_wordenc[(mt * 64 + row) * 512 + kc + kk];
            Bs[kk * 68 + row] = waW[(n0 + row) * 512 + kc + kk];
        }
        __syncthreads();
#pragma unroll
        for (int kk = 0; kk < 32; kk++) {
            float4 a = *(const float4*)&As[kk * 68 + ty * 4];
            float4 b = *(const float4*)&Bs[kk * 68 + tx * 4];
            float av[4] = {a.x, a.y, a.z, a.w};
            float bv[4] = {b.x, b.y, b.z, b.w};
#pragma unroll
            for (int i = 0; i < 4; i++)
#pragma unroll
                for (int j = 0; j < 4; j++) acc[i][j] += av[i] * bv[j];
        }
        __syncthreads();
    }
    float4 bb = *(const float4*)&wab[n0 + tx * 4];
    float bv[4] = {bb.x, bb.y, bb.z, bb.w};
    float cs[4] = {};
#pragma unroll
    for (int i = 0; i < 4; i++)
#pragma unroll
        for (int j = 0; j < 4; j++) cs[j] += tanhf(acc[i][j] + bv[j]);
#pragma unroll
    for (int j = 0; j < 4; j++) red2[ty * 64 + tx * 4 + j] = cs[j];
    __syncthreads();
    if (tid < 64) {
        float v = 0.f;
#pragma unroll
        for (int q = 0; q < 16; q++) v += red2[q * 64 + tid];
        int s = mt >> 1;
        atomicAdd(&g_sentsumm[s * 512 + n0 + tid], v);
    }
}

// ---------------- K4: sentence gi[d][s][n] = sent_summ @ sWi[d]^T + sbi[d] ----------------
__global__ void __launch_bounds__(256) k_sgi(const float* __restrict__ sWi,
                                             const float* __restrict__ sbi) {
    int n0 = blockIdx.x * 64, d = blockIdx.y;
    __shared__ float As[32 * 68];
    __shared__ float Bs[32 * 68];
    int tid = threadIdx.x, tx = tid & 15, ty = tid >> 4;
    float acc[4][4] = {};
    for (int kc = 0; kc < 512; kc += 32) {
        for (int e = tid; e < 2048; e += 256) {
            int row = e >> 5, kk = e & 31;
            As[kk * 68 + row] = g_sentsumm[row * 512 + kc + kk];
            Bs[kk * 68 + row] = sWi[(d * 1536 + n0 + row) * 512 + kc + kk];
        }
        __syncthreads();
#pragma unroll
        for (int kk = 0; kk < 32; kk++) {
            float4 a = *(const float4*)&As[kk * 68 + ty * 4];
            float4 b = *(const float4*)&Bs[kk * 68 + tx * 4];
            float av[4] = {a.x, a.y, a.z, a.w};
            float bv[4] = {b.x, b.y, b.z, b.w};
#pragma unroll
            for (int i = 0; i < 4; i++)
#pragma unroll
                for (int j = 0; j < 4; j++) acc[i][j] += av[i] * bv[j];
        }
        __syncthreads();
    }
    float4 bb = *(const float4*)&sbi[d * 1536 + n0 + tx * 4];
    float bvv[4] = {bb.x, bb.y, bb.z, bb.w};
#pragma unroll
    for (int i = 0; i < 4; i++) {
        int s = ty * 4 + i;
        float4 v = make_float4(acc[i][0] + bvv[0], acc[i][1] + bvv[1],
                               acc[i][2] + bvv[2], acc[i][3] + bvv[3]);
        *(float4*)&g_gis[(d * SS + s) * 1536 + n0 + tx * 4] = v;
    }
}

// ---------------- K5: sentence GRU-cell gates (zero state) ----------------
__global__ void k_sgates(const float* __restrict__ sbh) {
    int idx = blockIdx.x * blockDim.x + threadIdx.x;   // 65536
    int d = idx >> 15, r = idx & 32767, s = r >> 9, j = r & 511;
    const float* gi = g_gis + (d * SS + s) * 1536;
    float hr = sbh[d * 1536 + j], hz = sbh[d * 1536 + 512 + j], hn = sbh[d * 1536 + 1024 + j];
    float rr = fsig(gi[j] + hr);
    float z = fsig(gi[j + 512] + hz);
    float n = tanhf(gi[j + 1024] + rr * hn);
    g_sentenc[s * 1024 + d * 512 + j] = (1.0f - z) * n;
}

// ---------------- K6: u_sent = tanh(sentenc @ saW^T + sab) ----------------
__global__ void __launch_bounds__(256) k_usent(const float* __restrict__ saW,
                                               const float* __restrict__ sab) {
    int n0 = blockIdx.x * 64;
    __shared__ float As[32 * 68];
    __shared__ float Bs[32 * 68];
    int tid = threadIdx.x, tx = tid & 15, ty = tid >> 4;
    float acc[4][4] = {};
    for (int kc = 0; kc < 1024; kc += 32) {
        for (int e = tid; e < 2048; e += 256) {
            int row = e >> 5, kk = e & 31;
            As[kk * 68 + row] = g_sentenc[row * 1024 + kc + kk];
            Bs[kk * 68 + row] = saW[(n0 + row) * 1024 + kc + kk];
        }
        __syncthreads();
#pragma unroll
        for (int kk = 0; kk < 32; kk++) {
            float4 a = *(const float4*)&As[kk * 68 + ty * 4];
            float4 b = *(const float4*)&Bs[kk * 68 + tx * 4];
            float av[4] = {a.x, a.y, a.z, a.w};
            float bv[4] = {b.x, b.y, b.z, b.w};
#pragma unroll
            for (int i = 0; i < 4; i++)
#pragma unroll
                for (int j = 0; j < 4; j++) acc[i][j] += av[i] * bv[j];
        }
        __syncthreads();
    }
    float4 bb = *(const float4*)&sab[n0 + tx * 4];
    float bvv[4] = {bb.x, bb.y, bb.z, bb.w};
#pragma unroll
    for (int i = 0; i < 4; i++) {
        int s = ty * 4 + i;
#pragma unroll
        for (int j = 0; j < 4; j++)
            g_usent[s * 1024 + n0 + tx * 4 + j] = tanhf(acc[i][j] + bvv[j]);
    }
}

// ---------------- K7: doc[n] = sum_s u_sent[s][n] ----------------
__global__ void k_docsum() {
    int n = blockIdx.x * blockDim.x + threadIdx.x;   // 1024
    float v = 0.f;
#pragma unroll 8
    for (int s = 0; s < SS; s++) v += g_usent[s * 1024 + n];
    g_doc[n] = v;
}

// ---------------- K8: logits + log_softmax ----------------
__global__ void k_final(const float* __restrict__ doW, const float* __restrict__ dob,
                        float* __restrict__ out) {
    __shared__ float lg[16];
    int warp = threadIdx.x >> 5, lane = threadIdx.x & 31;
    for (int c = warp; c < NC; c += 8) {
        float v = 0.f;
        for (int n = lane; n < 1024; n += 32) v += g_doc[n] * doW[c * 1024 + n];
#pragma unroll
        for (int o = 16; o; o >>= 1) v += __shfl_xor_sync(0xffffffff, v, o);
        if (lane == 0) lg[c] = v + dob[c];
    }
    __syncthreads();
    if (threadIdx.x == 0) {
        float mx = -1e30f;
        for (int c = 0; c < NC; c++) mx = fmaxf(mx, lg[c]);
        float se = 0.f;
        for (int c = 0; c < NC; c++) se += expf(lg[c] - mx);
        float lse = mx + logf(se);
        for (int c = 0; c < NC; c++) out[8256 + c] = lg[c] - lse;
    }
}

extern "C" void kernel_launch(void* const* d_in, const int* in_sizes, int n_in,
                              void* d_out, int out_size) {
    const int*   doc = (const int*)d_in[0];
    const float* emb = (const float*)d_in[1];
    const float* wWi = (const float*)d_in[2];
    const float* wWh = (const float*)d_in[3];
    const float* wbi = (const float*)d_in[4];
    const float* wbh = (const float*)d_in[5];
    const float* sWi = (const float*)d_in[6];
    const float* sbi = (const float*)d_in[8];
    const float* sbh = (const float*)d_in[9];
    const float* waW = (const float*)d_in[10];
    const float* wab = (const float*)d_in[11];
    const float* saW = (const float*)d_in[13];
    const float* sab = (const float*)d_in[14];
    const float* doW = (const float*)d_in[16];
    const float* dob = (const float*)d_in[17];
    float* out = (float*)d_out;

    k_init<<<128, 256>>>(out);
    k_gi<<<dim3(12, 128, 2), 256>>>(doc, emb, wWi, wbi);
    k_recur<<<128, 256>>>(wWh, wbh);
    k_uword<<<dim3(8, 128), 256>>>(waW, wab);
    k_sgi<<<dim3(24, 2), 256>>>(sWi, sbi);
    k_sgates<<<256, 256>>>(sbh);
    k_usent<<<16, 256>>>(saW, sab);
    k_docsum<<<4, 256>>>();
    k_final<<<1, 256>>>(doW, dob, out);
}

// round 5
// speedup vs baseline: 1.1456x; 1.0687x over previous
#include <cuda_runtime.h>
#include <math.h>

#define SS 64
#define WW 128
#define DD 256
#define HWW 256
#define NC 13

// ---------------- scratch ----------------
__device__ float g_gi[2 * WW * SS * 768];      // [d][w][s][768]  (= [d][m=w*64+s][768])
__device__ float g_wordenc[SS * WW * 512];     // [s*128+w][512]
__device__ float g_sentsumm[SS * 512];         // [s][512]
__device__ float g_gis[2 * SS * 1536];         // [d][s][1536]
__device__ float g_sentenc[SS * 1024];         // [s][1024]
__device__ float g_usent[SS * 1024];           // [s][1024]
__device__ float g_doc[1024];

__device__ __forceinline__ float fsig(float x) {
    return __fdividef(1.0f, 1.0f + __expf(-x));
}
__device__ __forceinline__ float ftanh(float x) {
    return 1.0f - __fdividef(2.0f, __expf(2.0f * x) + 1.0f);
}

__device__ __forceinline__ unsigned long long ffma2(unsigned long long a,
                                                    unsigned long long b,
                                                    unsigned long long c) {
    unsigned long long d;
    asm("fma.rn.f32x2 %0, %1, %2, %3;" : "=l"(d) : "l"(a), "l"(b), "l"(c));
    return d;
}

__device__ __forceinline__ unsigned smem_u32(const void* p) {
    unsigned a;
    asm("{ .reg .u64 t; cvta.to.shared.u64 t, %1; cvt.u32.u64 %0, t; }" : "=r"(a) : "l"(p));
    return a;
}

// ---------------- init ----------------
__global__ void k_init(float* __restrict__ out) {
    int i = blockIdx.x * blockDim.x + threadIdx.x;
    if (i < 8256) out[i] = 1.0f;   // word_w + sent_w are softmax over size-1 axis -> ones
}

// ---------------- K1: gi[d][m][n] = emb[doc[m]] @ wWi[d]^T + wbi[d],  m = w*64+s -------
// GEMM M=8192, N=768, K=256. Tile 128x128, 8x8/thread. grid (6 nt, 64 mt, 2 d).
__global__ void __launch_bounds__(256) k_gi(const int* __restrict__ doc,
                                            const float* __restrict__ emb,
                                            const float* __restrict__ wWi,
                                            const float* __restrict__ wbi) {
    int n0 = blockIdx.x * 128, mt = blockIdx.y, d = blockIdx.z;
    __shared__ float As[16 * 132];
    __shared__ float Bs[16 * 132];
    __shared__ int toks[128];
    int tid = threadIdx.x;
    if (tid < 128) {
        int m = mt * 128 + tid;                  // w = m>>6, s = m&63
        toks[tid] = doc[(m & 63) * WW + (m >> 6)];
    }
    __syncthreads();
    int tx = tid & 15, ty = tid >> 4;
    int lrow = tid >> 1, kk0 = (tid & 1) * 8;
    const float* arow = emb + (long)toks[lrow] * DD;
    const float* brow = wWi + (d * 768 + n0 + lrow) * 256;
    float acc[8][8] = {};
    for (int kc = 0; kc < 256; kc += 16) {
        float4 a0 = *(const float4*)(arow + kc + kk0);
        float4 a1 = *(const float4*)(arow + kc + kk0 + 4);
        float4 b0 = *(const float4*)(brow + kc + kk0);
        float4 b1 = *(const float4*)(brow + kc + kk0 + 4);
        float am[8] = {a0.x, a0.y, a0.z, a0.w, a1.x, a1.y, a1.z, a1.w};
        float bm[8] = {b0.x, b0.y, b0.z, b0.w, b1.x, b1.y, b1.z, b1.w};
#pragma unroll
        for (int u = 0; u < 8; u++) {
            As[(kk0 + u) * 132 + lrow] = am[u];
            Bs[(kk0 + u) * 132 + lrow] = bm[u];
        }
        __syncthreads();
#pragma unroll
        for (int kk = 0; kk < 16; kk++) {
            float4 x0 = *(const float4*)&As[kk * 132 + ty * 8];
            float4 x1 = *(const float4*)&As[kk * 132 + ty * 8 + 4];
            float4 y0 = *(const float4*)&Bs[kk * 132 + tx * 8];
            float4 y1 = *(const float4*)&Bs[kk * 132 + tx * 8 + 4];
            float av[8] = {x0.x, x0.y, x0.z, x0.w, x1.x, x1.y, x1.z, x1.w};
            float bv[8] = {y0.x, y0.y, y0.z, y0.w, y1.x, y1.y, y1.z, y1.w};
#pragma unroll
            for (int i = 0; i < 8; i++)
#pragma unroll
                for (int j = 0; j < 8; j++) acc[i][j] += av[i] * bv[j];
        }
        __syncthreads();
    }
    float4 c0 = *(const float4*)&wbi[d * 768 + n0 + tx * 8];
    float4 c1 = *(const float4*)&wbi[d * 768 + n0 + tx * 8 + 4];
    float bb[8] = {c0.x, c0.y, c0.z, c0.w, c1.x, c1.y, c1.z, c1.w};
#pragma unroll
    for (int i = 0; i < 8; i++) {
        int m = mt * 128 + ty * 8 + i;
        float* dst = g_gi + ((long)d * 8192 + m) * 768 + n0 + tx * 8;
        float4 v0 = make_float4(acc[i][0] + bb[0], acc[i][1] + bb[1],
                                acc[i][2] + bb[2], acc[i][3] + bb[3]);
        float4 v1 = make_float4(acc[i][4] + bb[4], acc[i][5] + bb[5],
                                acc[i][6] + bb[6], acc[i][7] + bb[7]);
        *(float4*)dst = v0;
        *(float4*)(dst + 4) = v1;
    }
}

// ---------------- K2: persistent word-GRU recurrence (clusters of 8, DSMEM h exchange) ----
__global__ void __launch_bounds__(256, 1) __cluster_dims__(8, 1, 1)
k_recur(const float* __restrict__ wWh, const float* __restrict__ wbh) {
    __shared__ float h_sm[2][2048];        // ping-pong [buf][s_loc*256 + j]
    __shared__ float red_sm[32 * 201];     // [j_loc][(g*8+s)*8 + ks]
    int c = blockIdx.x;
    int d = c >> 6, sb = (c >> 3) & 7, jb = c & 7;
    int tid = threadIdx.x;
    int ks = tid >> 5, lane = tid & 31;
    int sb8 = sb * 8;

    unsigned long long whr2[3][16];
#pragma unroll
    for (int g = 0; g < 3; g++) {
        const unsigned long long* wr = (const unsigned long long*)
            (wWh + (d * 768 + g * 256 + jb * 32 + lane) * 256 + ks * 32);
#pragma unroll
        for (int t = 0; t < 16; t++) whr2[g][t] = wr[t];
    }

    int s2 = tid >> 5, j2 = tid & 31;
    int jg2 = jb * 32 + j2;
    float bhr = wbh[d * 768 + jg2];
    float bhz = wbh[d * 768 + 256 + jg2];
    float bhn = wbh[d * 768 + 512 + jg2];

#pragma unroll
    for (int q = 0; q < 8; q++) h_sm[0][tid * 8 + q] = 0.0f;

    unsigned my_base = smem_u32(&h_sm[0][0]);
    unsigned elem_off = (unsigned)(s2 * 256 + jg2) * 4u;
    unsigned pa[8];
#pragma unroll
    for (int r = 0; r < 8; r++) {
        unsigned peer;
        asm("mapa.shared::cluster.u32 %0, %1, %2;" : "=r"(peer) : "r"(my_base), "r"(r));
        pa[r] = peer + elem_off;
    }
    __syncthreads();

    int p = 0;
    for (int w = 0; w < WW; w++) {
        const float* gi = g_gi + ((d * WW + w) * SS + (sb8 + s2)) * 768 + jg2;
        float gi0 = __ldg(gi);
        float gi1 = __ldg(gi + 256);
        float gi2 = __ldg(gi + 512);

        const float* hb = &h_sm[p][ks * 32];
        unsigned long long acc2[3][8];
#pragma unroll
        for (int g = 0; g < 3; g++)
#pragma unroll
            for (int s = 0; s < 8; s++) acc2[g][s] = 0ull;
#pragma unroll
        for (int kk4 = 0; kk4 < 8; kk4++) {
#pragma unroll
            for (int s = 0; s < 8; s++) {
                ulonglong2 hv = *(const ulonglong2*)(hb + s * 256 + kk4 * 4);
#pragma unroll
                for (int g = 0; g < 3; g++) {
                    acc2[g][s] = ffma2(hv.x, whr2[g][kk4 * 2], acc2[g][s]);
                    acc2[g][s] = ffma2(hv.y, whr2[g][kk4 * 2 + 1], acc2[g][s]);
                }
            }
        }
#pragma unroll
        for (int g = 0; g < 3; g++)
#pragma unroll
            for (int s = 0; s < 8; s++) {
                float2 f = *(float2*)&acc2[g][s];
                red_sm[lane * 201 + (g * 8 + s) * 8 + ks] = f.x + f.y;
            }
        __syncthreads();

        float gh[3];
#pragma unroll
        for (int g = 0; g < 3; g++) {
            float v = 0.f;
#pragma unroll
            for (int q = 0; q < 8; q++) v += red_sm[j2 * 201 + (g * 8 + s2) * 8 + q];
            gh[g] = v;
        }
        float h_old = h_sm[p][s2 * 256 + jg2];
        float r = fsig(gi0 + gh[0] + bhr);
        float z = fsig(gi1 + gh[1] + bhz);
        float n = ftanh(gi2 + r * (gh[2] + bhn));
        float hn = (1.0f - z) * n + z * h_old;

        unsigned poff = (unsigned)((p ^ 1) * 8192);
#pragma unroll
        for (int r8 = 0; r8 < 8; r8++)
            asm volatile("st.shared::cluster.f32 [%0], %1;" :: "r"(pa[r8] + poff), "f"(hn));
        g_wordenc[((sb8 + s2) * WW + w) * 512 + d * 256 + jg2] = hn;

        asm volatile("barrier.cluster.arrive.aligned;" ::: "memory");
        asm volatile("barrier.cluster.wait.aligned;" ::: "memory");
        p ^= 1;
    }
}

// ---------------- K3: u_word GEMM + fused per-sentence reduction --------------------------
// GEMM M=8192 (rows s*128+w), N=512, K=512. Tile 128x128 -> one m-tile == one sentence.
// grid (4 nt, 64 mt). Direct store to g_sentsumm (no atomics).
__global__ void __launch_bounds__(256) k_uword(const float* __restrict__ waW,
                                               const float* __restrict__ wab) {
    int n0 = blockIdx.x * 128, mt = blockIdx.y;
    __shared__ float As[16 * 132];
    __shared__ float Bs[16 * 132];
    int tid = threadIdx.x;
    int tx = tid & 15, ty = tid >> 4;
    int lrow = tid >> 1, kk0 = (tid & 1) * 8;
    const float* arow = g_wordenc + (mt * 128 + lrow) * 512;
    const float* brow = waW + (n0 + lrow) * 512;
    float acc[8][8] = {};
    for (int kc = 0; kc < 512; kc += 16) {
        float4 a0 = *(const float4*)(arow + kc + kk0);
        float4 a1 = *(const float4*)(arow + kc + kk0 + 4);
        float4 b0 = *(const float4*)(brow + kc + kk0);
        float4 b1 = *(const float4*)(brow + kc + kk0 + 4);
        float am[8] = {a0.x, a0.y, a0.z, a0.w, a1.x, a1.y, a1.z, a1.w};
        float bm[8] = {b0.x, b0.y, b0.z, b0.w, b1.x, b1.y, b1.z, b1.w};
#pragma unroll
        for (int u = 0; u < 8; u++) {
            As[(kk0 + u) * 132 + lrow] = am[u];
            Bs[(kk0 + u) * 132 + lrow] = bm[u];
        }
        __syncthreads();
#pragma unroll
        for (int kk = 0; kk < 16; kk++) {
            float4 x0 = *(const float4*)&As[kk * 132 + ty * 8];
            float4 x1 = *(const float4*)&As[kk * 132 + ty * 8 + 4];
            float4 y0 = *(const float4*)&Bs[kk * 132 + tx * 8];
            float4 y1 = *(const float4*)&Bs[kk * 132 + tx * 8 + 4];
            float av[8] = {x0.x, x0.y, x0.z, x0.w, x1.x, x1.y, x1.z, x1.w};
            float bv[8] = {y0.x, y0.y, y0.z, y0.w, y1.x, y1.y, y1.z, y1.w};
#pragma unroll
            for (int i = 0; i < 8; i++)
#pragma unroll
                for (int j = 0; j < 8; j++) acc[i][j] += av[i] * bv[j];
        }
        __syncthreads();
    }
    float4 c0 = *(const float4*)&wab[n0 + tx * 8];
    float4 c1 = *(const float4*)&wab[n0 + tx * 8 + 4];
    float bb[8] = {c0.x, c0.y, c0.z, c0.w, c1.x, c1.y, c1.z, c1.w};
    float cs[8] = {};
#pragma unroll
    for (int i = 0; i < 8; i++)
#pragma unroll
        for (int j = 0; j < 8; j++) cs[j] += ftanh(acc[i][j] + bb[j]);
    // reduce the 16 ty-groups via smem (reuse As)
#pragma unroll
    for (int j = 0; j < 8; j++) As[ty * 128 + tx * 8 + j] = cs[j];
    __syncthreads();
    if (tid < 128) {
        float v = 0.f;
#pragma unroll
        for (int q = 0; q < 16; q++) v += As[q * 128 + tid];
        g_sentsumm[mt * 512 + n0 + tid] = v;   // m-tile == sentence mt, cols owned uniquely
    }
}

// ---------------- K4: sentence gi[d][s][n] = sent_summ @ sWi[d]^T + sbi[d] ----------------
__global__ void __launch_bounds__(256) k_sgi(const float* __restrict__ sWi,
                                             const float* __restrict__ sbi) {
    int n0 = blockIdx.x * 64, d = blockIdx.y;
    __shared__ float As[32 * 68];
    __shared__ float Bs[32 * 68];
    int tid = threadIdx.x, tx = tid & 15, ty = tid >> 4;
    float acc[4][4] = {};
    for (int kc = 0; kc < 512; kc += 32) {
        for (int e = tid; e < 2048; e += 256) {
            int row = e >> 5, kk = e & 31;
            As[kk * 68 + row] = g_sentsumm[row * 512 + kc + kk];
            Bs[kk * 68 + row] = sWi[(d * 1536 + n0 + row) * 512 + kc + kk];
        }
        __syncthreads();
#pragma unroll
        for (int kk = 0; kk < 32; kk++) {
            float4 a = *(const float4*)&As[kk * 68 + ty * 4];
            float4 b = *(const float4*)&Bs[kk * 68 + tx * 4];
            float av[4] = {a.x, a.y, a.z, a.w};
            float bv[4] = {b.x, b.y, b.z, b.w};
#pragma unroll
            for (int i = 0; i < 4; i++)
#pragma unroll
                for (int j = 0; j < 4; j++) acc[i][j] += av[i] * bv[j];
        }
        __syncthreads();
    }
    float4 bbv = *(const float4*)&sbi[d * 1536 + n0 + tx * 4];
    float bvv[4] = {bbv.x, bbv.y, bbv.z, bbv.w};
#pragma unroll
    for (int i = 0; i < 4; i++) {
        int s = ty * 4 + i;
        float4 v = make_float4(acc[i][0] + bvv[0], acc[i][1] + bvv[1],
                               acc[i][2] + bvv[2], acc[i][3] + bvv[3]);
        *(float4*)&g_gis[(d * SS + s) * 1536 + n0 + tx * 4] = v;
    }
}

// ---------------- K5: sentence GRU-cell gates (zero state) ----------------
__global__ void k_sgates(const float* __restrict__ sbh) {
    int idx = blockIdx.x * blockDim.x + threadIdx.x;   // 65536
    int d = idx >> 15, r = idx & 32767, s = r >> 9, j = r & 511;
    const float* gi = g_gis + (d * SS + s) * 1536;
    float hr = sbh[d * 1536 + j], hz = sbh[d * 1536 + 512 + j], hn = sbh[d * 1536 + 1024 + j];
    float rr = fsig(gi[j] + hr);
    float z = fsig(gi[j + 512] + hz);
    float n = ftanh(gi[j + 1024] + rr * hn);
    g_sentenc[s * 1024 + d * 512 + j] = (1.0f - z) * n;
}

// ---------------- K6: u_sent = tanh(sentenc @ saW^T + sab) ----------------
__global__ void __launch_bounds__(256) k_usent(const float* __restrict__ saW,
                                               const float* __restrict__ sab) {
    int n0 = blockIdx.x * 64;
    __shared__ float As[32 * 68];
    __shared__ float Bs[32 * 68];
    int tid = threadIdx.x, tx = tid & 15, ty = tid >> 4;
    float acc[4][4] = {};
    for (int kc = 0; kc < 1024; kc += 32) {
        for (int e = tid; e < 2048; e += 256) {
            int row = e >> 5, kk = e & 31;
            As[kk * 68 + row] = g_sentenc[row * 1024 + kc + kk];
            Bs[kk * 68 + row] = saW[(n0 + row) * 1024 + kc + kk];
        }
        __syncthreads();
#pragma unroll
        for (int kk = 0; kk < 32; kk++) {
            float4 a = *(const float4*)&As[kk * 68 + ty * 4];
            float4 b = *(const float4*)&Bs[kk * 68 + tx * 4];
            float av[4] = {a.x, a.y, a.z, a.w};
            float bv[4] = {b.x, b.y, b.z, b.w};
#pragma unroll
            for (int i = 0; i < 4; i++)
#pragma unroll
                for (int j = 0; j < 4; j++) acc[i][j] += av[i] * bv[j];
        }
        __syncthreads();
    }
    float4 bbv = *(const float4*)&sab[n0 + tx * 4];
    float bvv[4] = {bbv.x, bbv.y, bbv.z, bbv.w};
#pragma unroll
    for (int i = 0; i < 4; i++) {
        int s = ty * 4 + i;
#pragma unroll
        for (int j = 0; j < 4; j++)
            g_usent[s * 1024 + n0 + tx * 4 + j] = ftanh(acc[i][j] + bvv[j]);
    }
}

// ---------------- K7: doc[n] = sum_s u_sent[s][n] ----------------
__global__ void k_docsum() {
    int n = blockIdx.x * blockDim.x + threadIdx.x;   // 1024
    float v = 0.f;
#pragma unroll 8
    for (int s = 0; s < SS; s++) v += g_usent[s * 1024 + n];
    g_doc[n] = v;
}

// ---------------- K8: logits + log_softmax ----------------
__global__ void k_final(const float* __restrict__ doW, const float* __restrict__ dob,
                        float* __restrict__ out) {
    __shared__ float lg[16];
    int warp = threadIdx.x >> 5, lane = threadIdx.x & 31;
    for (int c = warp; c < NC; c += 8) {
        float v = 0.f;
        for (int n = lane; n < 1024; n += 32) v += g_doc[n] * doW[c * 1024 + n];
#pragma unroll
        for (int o = 16; o; o >>= 1) v += __shfl_xor_sync(0xffffffff, v, o);
        if (lane == 0) lg[c] = v + dob[c];
    }
    __syncthreads();
    if (threadIdx.x == 0) {
        float mx = -1e30f;
        for (int c = 0; c < NC; c++) mx = fmaxf(mx, lg[c]);
        float se = 0.f;
        for (int c = 0; c < NC; c++) se += expf(lg[c] - mx);
        float lse = mx + logf(se);
        for (int c = 0; c < NC; c++) out[8256 + c] = lg[c] - lse;
    }
}

extern "C" void kernel_launch(void* const* d_in, const int* in_sizes, int n_in,
                              void* d_out, int out_size) {
    const int*   doc = (const int*)d_in[0];
    const float* emb = (const float*)d_in[1];
    const float* wWi = (const float*)d_in[2];
    const float* wWh = (const float*)d_in[3];
    const float* wbi = (const float*)d_in[4];
    const float* wbh = (const float*)d_in[5];
    const float* sWi = (const float*)d_in[6];
    const float* sbi = (const float*)d_in[8];
    const float* sbh = (const float*)d_in[9];
    const float* waW = (const float*)d_in[10];
    const float* wab = (const float*)d_in[11];
    const float* saW = (const float*)d_in[13];
    const float* sab = (const float*)d_in[14];
    const float* doW = (const float*)d_in[16];
    const float* dob = (const float*)d_in[17];
    float* out = (float*)d_out;

    k_init<<<64, 256>>>(out);
    k_gi<<<dim3(6, 64, 2), 256>>>(doc, emb, wWi, wbi);
    k_recur<<<128, 256>>>(wWh, wbh);
    k_uword<<<dim3(4, 64), 256>>>(waW, wab);
    k_sgi<<<dim3(24, 2), 256>>>(sWi, sbi);
    k_sgates<<<256, 256>>>(sbh);
    k_usent<<<16, 256>>>(saW, sab);
    k_docsum<<<4, 256>>>();
    k_final<<<1, 256>>>(doW, dob, out);
}

// round 7
// speedup vs baseline: 1.1551x; 1.0082x over previous
#include <cuda_runtime.h>
#include <math.h>

// Round 6 resubmission — prior attempt hit "GB300 container failed twice" (infra),
// kernel never ran. Identical content.

#define SS 64
#define WW 128
#define DD 256
#define HWW 256
#define NC 13

// ---------------- scratch ----------------
__device__ float g_gi[2 * WW * SS * 768];      // [d][w][s][768]  (= [d][m=w*64+s][768])
__device__ float g_wordenc[SS * WW * 512];     // [s*128+w][512]
__device__ float g_sentsumm[SS * 512];         // [s][512]
__device__ float g_gis[2 * SS * 1536];         // [d][s][1536]
__device__ float g_sentenc[SS * 1024];         // [s][1024]
__device__ float g_usent[SS * 1024];           // [s][1024]
__device__ float g_doc[1024];
__device__ float g_sink;

__device__ __forceinline__ float fsig(float x) {
    return __fdividef(1.0f, 1.0f + __expf(-x));
}
__device__ __forceinline__ float ftanh(float x) {
    return 1.0f - __fdividef(2.0f, __expf(2.0f * x) + 1.0f);
}

__device__ __forceinline__ unsigned long long ffma2(unsigned long long a,
                                                    unsigned long long b,
                                                    unsigned long long c) {
    unsigned long long d;
    asm("fma.rn.f32x2 %0, %1, %2, %3;" : "=l"(d) : "l"(a), "l"(b), "l"(c));
    return d;
}

__device__ __forceinline__ unsigned smem_u32(const void* p) {
    unsigned a;
    asm("{ .reg .u64 t; cvta.to.shared.u64 t, %1; cvt.u32.u64 %0, t; }" : "=r"(a) : "l"(p));
    return a;
}

// ---------------- init ----------------
__global__ void k_init(float* __restrict__ out) {
    int i = blockIdx.x * blockDim.x + threadIdx.x;
    if (i < 8256) out[i] = 1.0f;   // word_w + sent_w are softmax over size-1 axis -> ones
}

// dummy: shifts k_recur into the ncu-profiled launch slot
__global__ void k_dummy() { g_sink = 0.0f; }

// ---------------- K1: gi[d][m][n] = emb[doc[m]] @ wWi[d]^T + wbi[d],  m = w*64+s -------
// GEMM M=8192, N=768, K=256. Tile 128x128, 8x8/thread, software-pipelined loads.
__global__ void __launch_bounds__(256) k_gi(const int* __restrict__ doc,
                                            const float* __restrict__ emb,
                                            const float* __restrict__ wWi,
                                            const float* __restrict__ wbi) {
    int n0 = blockIdx.x * 128, mt = blockIdx.y, d = blockIdx.z;
    __shared__ float As[16 * 132];
    __shared__ float Bs[16 * 132];
    __shared__ int toks[128];
    int tid = threadIdx.x;
    if (tid < 128) {
        int m = mt * 128 + tid;                  // w = m>>6, s = m&63
        toks[tid] = doc[(m & 63) * WW + (m >> 6)];
    }
    __syncthreads();
    int tx = tid & 15, ty = tid >> 4;
    int lrow = tid >> 1, kk0 = (tid & 1) * 8;
    const float* arow = emb + (long)toks[lrow] * DD + kk0;
    const float* brow = wWi + (d * 768 + n0 + lrow) * 256 + kk0;
    float acc[8][8] = {};
    float4 a0 = *(const float4*)(arow);
    float4 a1 = *(const float4*)(arow + 4);
    float4 b0 = *(const float4*)(brow);
    float4 b1 = *(const float4*)(brow + 4);
    for (int kc = 0; kc < 256; kc += 16) {
        float am[8] = {a0.x, a0.y, a0.z, a0.w, a1.x, a1.y, a1.z, a1.w};
        float bm[8] = {b0.x, b0.y, b0.z, b0.w, b1.x, b1.y, b1.z, b1.w};
#pragma unroll
        for (int u = 0; u < 8; u++) {
            As[(kk0 + u) * 132 + lrow] = am[u];
            Bs[(kk0 + u) * 132 + lrow] = bm[u];
        }
        __syncthreads();
        if (kc + 16 < 256) {                       // prefetch next chunk during compute
            a0 = *(const float4*)(arow + kc + 16);
            a1 = *(const float4*)(arow + kc + 20);
            b0 = *(const float4*)(brow + kc + 16);
            b1 = *(const float4*)(brow + kc + 20);
        }
#pragma unroll
        for (int kk = 0; kk < 16; kk++) {
            float4 x0 = *(const float4*)&As[kk * 132 + ty * 8];
            float4 x1 = *(const float4*)&As[kk * 132 + ty * 8 + 4];
            float4 y0 = *(const float4*)&Bs[kk * 132 + tx * 8];
            float4 y1 = *(const float4*)&Bs[kk * 132 + tx * 8 + 4];
            float av[8] = {x0.x, x0.y, x0.z, x0.w, x1.x, x1.y, x1.z, x1.w};
            float bv[8] = {y0.x, y0.y, y0.z, y0.w, y1.x, y1.y, y1.z, y1.w};
#pragma unroll
            for (int i = 0; i < 8; i++)
#pragma unroll
                for (int j = 0; j < 8; j++) acc[i][j] += av[i] * bv[j];
        }
        __syncthreads();
    }
    float4 c0 = *(const float4*)&wbi[d * 768 + n0 + tx * 8];
    float4 c1 = *(const float4*)&wbi[d * 768 + n0 + tx * 8 + 4];
    float bb[8] = {c0.x, c0.y, c0.z, c0.w, c1.x, c1.y, c1.z, c1.w};
#pragma unroll
    for (int i = 0; i < 8; i++) {
        int m = mt * 128 + ty * 8 + i;
        float* dst = g_gi + ((long)d * 8192 + m) * 768 + n0 + tx * 8;
        float4 v0 = make_float4(acc[i][0] + bb[0], acc[i][1] + bb[1],
                                acc[i][2] + bb[2], acc[i][3] + bb[3]);
        float4 v1 = make_float4(acc[i][4] + bb[4], acc[i][5] + bb[5],
                                acc[i][6] + bb[6], acc[i][7] + bb[7]);
        *(float4*)dst = v0;
        *(float4*)(dst + 4) = v1;
    }
}

// ---------------- K2: persistent word-GRU recurrence (clusters of 8, DSMEM h exchange) ----
__global__ void __launch_bounds__(256, 1) __cluster_dims__(8, 1, 1)
k_recur(const float* __restrict__ wWh, const float* __restrict__ wbh) {
    __shared__ float h_sm[2][2048];        // ping-pong [buf][s_loc*256 + j]
    __shared__ float red_sm[32 * 201];     // [j_loc][(g*8+s)*8 + ks]
    int c = blockIdx.x;
    int d = c >> 6, sb = (c >> 3) & 7, jb = c & 7;
    int tid = threadIdx.x;
    int ks = tid >> 5, lane = tid & 31;
    int sb8 = sb * 8;

    unsigned long long whr2[3][16];
#pragma unroll
    for (int g = 0; g < 3; g++) {
        const unsigned long long* wr = (const unsigned long long*)
            (wWh + (d * 768 + g * 256 + jb * 32 + lane) * 256 + ks * 32);
#pragma unroll
        for (int t = 0; t < 16; t++) whr2[g][t] = wr[t];
    }

    int s2 = tid >> 5, j2 = tid & 31;
    int jg2 = jb * 32 + j2;
    float bhr = wbh[d * 768 + jg2];
    float bhz = wbh[d * 768 + 256 + jg2];
    float bhn = wbh[d * 768 + 512 + jg2];

#pragma unroll
    for (int q = 0; q < 8; q++) h_sm[0][tid * 8 + q] = 0.0f;

    unsigned my_base = smem_u32(&h_sm[0][0]);
    unsigned elem_off = (unsigned)(s2 * 256 + jg2) * 4u;
    unsigned pa[8];
#pragma unroll
    for (int r = 0; r < 8; r++) {
        unsigned peer;
        asm("mapa.shared::cluster.u32 %0, %1, %2;" : "=r"(peer) : "r"(my_base), "r"(r));
        pa[r] = peer + elem_off;
    }
    __syncthreads();

    int p = 0;
    for (int w = 0; w < WW; w++) {
        const float* gi = g_gi + ((d * WW + w) * SS + (sb8 + s2)) * 768 + jg2;
        float gi0 = __ldg(gi);
        float gi1 = __ldg(gi + 256);
        float gi2 = __ldg(gi + 512);

        const float* hb = &h_sm[p][ks * 32];
        unsigned long long acc2[3][8];
#pragma unroll
        for (int g = 0; g < 3; g++)
#pragma unroll
            for (int s = 0; s < 8; s++) acc2[g][s] = 0ull;
#pragma unroll
        for (int kk4 = 0; kk4 < 8; kk4++) {
#pragma unroll
            for (int s = 0; s < 8; s++) {
                ulonglong2 hv = *(const ulonglong2*)(hb + s * 256 + kk4 * 4);
#pragma unroll
                for (int g = 0; g < 3; g++) {
                    acc2[g][s] = ffma2(hv.x, whr2[g][kk4 * 2], acc2[g][s]);
                    acc2[g][s] = ffma2(hv.y, whr2[g][kk4 * 2 + 1], acc2[g][s]);
                }
            }
        }
#pragma unroll
        for (int g = 0; g < 3; g++)
#pragma unroll
            for (int s = 0; s < 8; s++) {
                float2 f = *(float2*)&acc2[g][s];
                red_sm[lane * 201 + (g * 8 + s) * 8 + ks] = f.x + f.y;
            }
        __syncthreads();

        float gh[3];
#pragma unroll
        for (int g = 0; g < 3; g++) {
            float v = 0.f;
#pragma unroll
            for (int q = 0; q < 8; q++) v += red_sm[j2 * 201 + (g * 8 + s2) * 8 + q];
            gh[g] = v;
        }
        float h_old = h_sm[p][s2 * 256 + jg2];
        float r = fsig(gi0 + gh[0] + bhr);
        float z = fsig(gi1 + gh[1] + bhz);
        float n = ftanh(gi2 + r * (gh[2] + bhn));
        float hn = (1.0f - z) * n + z * h_old;

        unsigned poff = (unsigned)((p ^ 1) * 8192);
#pragma unroll
        for (int r8 = 0; r8 < 8; r8++)
            asm volatile("st.shared::cluster.f32 [%0], %1;" :: "r"(pa[r8] + poff), "f"(hn));
        g_wordenc[((sb8 + s2) * WW + w) * 512 + d * 256 + jg2] = hn;

        asm volatile("barrier.cluster.arrive.aligned;" ::: "memory");
        asm volatile("barrier.cluster.wait.aligned;" ::: "memory");
        p ^= 1;
    }
}

// ---------------- K3: u_word GEMM + fused per-sentence reduction (pipelined) -------------
__global__ void __launch_bounds__(256) k_uword(const float* __restrict__ waW,
                                               const float* __restrict__ wab) {
    int n0 = blockIdx.x * 128, mt = blockIdx.y;
    __shared__ float As[16 * 132];
    __shared__ float Bs[16 * 132];
    int tid = threadIdx.x;
    int tx = tid & 15, ty = tid >> 4;
    int lrow = tid >> 1, kk0 = (tid & 1) * 8;
    const float* arow = g_wordenc + (mt * 128 + lrow) * 512 + kk0;
    const float* brow = waW + (n0 + lrow) * 512 + kk0;
    float acc[8][8] = {};
    float4 a0 = *(const float4*)(arow);
    float4 a1 = *(const float4*)(arow + 4);
    float4 b0 = *(const float4*)(brow);
    float4 b1 = *(const float4*)(brow + 4);
    for (int kc = 0; kc < 512; kc += 16) {
        float am[8] = {a0.x, a0.y, a0.z, a0.w, a1.x, a1.y, a1.z, a1.w};
        float bm[8] = {b0.x, b0.y, b0.z, b0.w, b1.x, b1.y, b1.z, b1.w};
#pragma unroll
        for (int u = 0; u < 8; u++) {
            As[(kk0 + u) * 132 + lrow] = am[u];
            Bs[(kk0 + u) * 132 + lrow] = bm[u];
        }
        __syncthreads();
        if (kc + 16 < 512) {
            a0 = *(const float4*)(arow + kc + 16);
            a1 = *(const float4*)(arow + kc + 20);
            b0 = *(const float4*)(brow + kc + 16);
            b1 = *(const float4*)(brow + kc + 20);
        }
#pragma unroll
        for (int kk = 0; kk < 16; kk++) {
            float4 x0 = *(const float4*)&As[kk * 132 + ty * 8];
            float4 x1 = *(const float4*)&As[kk * 132 + ty * 8 + 4];
            float4 y0 = *(const float4*)&Bs[kk * 132 + tx * 8];
            float4 y1 = *(const float4*)&Bs[kk * 132 + tx * 8 + 4];
            float av[8] = {x0.x, x0.y, x0.z, x0.w, x1.x, x1.y, x1.z, x1.w};
            float bv[8] = {y0.x, y0.y, y0.z, y0.w, y1.x, y1.y, y1.z, y1.w};
#pragma unroll
            for (int i = 0; i < 8; i++)
#pragma unroll
                for (int j = 0; j < 8; j++) acc[i][j] += av[i] * bv[j];
        }
        __syncthreads();
    }
    float4 c0 = *(const float4*)&wab[n0 + tx * 8];
    float4 c1 = *(const float4*)&wab[n0 + tx * 8 + 4];
    float bb[8] = {c0.x, c0.y, c0.z, c0.w, c1.x, c1.y, c1.z, c1.w};
    float cs[8] = {};
#pragma unroll
    for (int i = 0; i < 8; i++)
#pragma unroll
        for (int j = 0; j < 8; j++) cs[j] += ftanh(acc[i][j] + bb[j]);
#pragma unroll
    for (int j = 0; j < 8; j++) As[ty * 128 + tx * 8 + j] = cs[j];
    __syncthreads();
    if (tid < 128) {
        float v = 0.f;
#pragma unroll
        for (int q = 0; q < 16; q++) v += As[q * 128 + tid];
        g_sentsumm[mt * 512 + n0 + tid] = v;   // m-tile == sentence mt
    }
}

// ---------------- K4: sentence gi[d][s][n] = sent_summ @ sWi[d]^T + sbi[d] ----------------
__global__ void __launch_bounds__(256) k_sgi(const float* __restrict__ sWi,
                                             const float* __restrict__ sbi) {
    int n0 = blockIdx.x * 64, d = blockIdx.y;
    __shared__ float As[32 * 68];
    __shared__ float Bs[32 * 68];
    int tid = threadIdx.x, tx = tid & 15, ty = tid >> 4;
    float acc[4][4] = {};
    for (int kc = 0; kc < 512; kc += 32) {
        for (int e = tid; e < 2048; e += 256) {
            int row = e >> 5, kk = e & 31;
            As[kk * 68 + row] = g_sentsumm[row * 512 + kc + kk];
            Bs[kk * 68 + row] = sWi[(d * 1536 + n0 + row) * 512 + kc + kk];
        }
        __syncthreads();
#pragma unroll
        for (int kk = 0; kk < 32; kk++) {
            float4 a = *(const float4*)&As[kk * 68 + ty * 4];
            float4 b = *(const float4*)&Bs[kk * 68 + tx * 4];
            float av[4] = {a.x, a.y, a.z, a.w};
            float bv[4] = {b.x, b.y, b.z, b.w};
#pragma unroll
            for (int i = 0; i < 4; i++)
#pragma unroll
                for (int j = 0; j < 4; j++) acc[i][j] += av[i] * bv[j];
        }
        __syncthreads();
    }
    float4 bbv = *(const float4*)&sbi[d * 1536 + n0 + tx * 4];
    float bvv[4] = {bbv.x, bbv.y, bbv.z, bbv.w};
#pragma unroll
    for (int i = 0; i < 4; i++) {
        int s = ty * 4 + i;
        float4 v = make_float4(acc[i][0] + bvv[0], acc[i][1] + bvv[1],
                               acc[i][2] + bvv[2], acc[i][3] + bvv[3]);
        *(float4*)&g_gis[(d * SS + s) * 1536 + n0 + tx * 4] = v;
    }
}

// ---------------- K5: sentence GRU-cell gates (zero state) ----------------
__global__ void k_sgates(const float* __restrict__ sbh) {
    int idx = blockIdx.x * blockDim.x + threadIdx.x;   // 65536
    int d = idx >> 15, r = idx & 32767, s = r >> 9, j = r & 511;
    const float* gi = g_gis + (d * SS + s) * 1536;
    float hr = sbh[d * 1536 + j], hz = sbh[d * 1536 + 512 + j], hn = sbh[d * 1536 + 1024 + j];
    float rr = fsig(gi[j] + hr);
    float z = fsig(gi[j + 512] + hz);
    float n = ftanh(gi[j + 1024] + rr * hn);
    g_sentenc[s * 1024 + d * 512 + j] = (1.0f - z) * n;
}

// ---------------- K6: u_sent = tanh(sentenc @ saW^T + sab) ----------------
__global__ void __launch_bounds__(256) k_usent(const float* __restrict__ saW,
                                               const float* __restrict__ sab) {
    int n0 = blockIdx.x * 64;
    __shared__ float As[32 * 68];
    __shared__ float Bs[32 * 68];
    int tid = threadIdx.x, tx = tid & 15, ty = tid >> 4;
    float acc[4][4] = {};
    for (int kc = 0; kc < 1024; kc += 32) {
        for (int e = tid; e < 2048; e += 256) {
            int row = e >> 5, kk = e & 31;
            As[kk * 68 + row] = g_sentenc[row * 1024 + kc + kk];
            Bs[kk * 68 + row] = saW[(n0 + row) * 1024 + kc + kk];
        }
        __syncthreads();
#pragma unroll
        for (int kk = 0; kk < 32; kk++) {
            float4 a = *(const float4*)&As[kk * 68 + ty * 4];
            float4 b = *(const float4*)&Bs[kk * 68 + tx * 4];
            float av[4] = {a.x, a.y, a.z, a.w};
            float bv[4] = {b.x, b.y, b.z, b.w};
#pragma unroll
            for (int i = 0; i < 4; i++)
#pragma unroll
                for (int j = 0; j < 4; j++) acc[i][j] += av[i] * bv[j];
        }
        __syncthreads();
    }
    float4 bbv = *(const float4*)&sab[n0 + tx * 4];
    float bvv[4] = {bbv.x, bbv.y, bbv.z, bbv.w};
#pragma unroll
    for (int i = 0; i < 4; i++) {
        int s = ty * 4 + i;
#pragma unroll
        for (int j = 0; j < 4; j++)
            g_usent[s * 1024 + n0 + tx * 4 + j] = ftanh(acc[i][j] + bvv[j]);
    }
}

// ---------------- K7: doc[n] = sum_s u_sent[s][n] ----------------
__global__ void k_docsum() {
    int n = blockIdx.x * blockDim.x + threadIdx.x;   // 1024
    float v = 0.f;
#pragma unroll 8
    for (int s = 0; s < SS; s++) v += g_usent[s * 1024 + n];
    g_doc[n] = v;
}

// ---------------- K8: logits + log_softmax ----------------
__global__ void k_final(const float* __restrict__ doW, const float* __restrict__ dob,
                        float* __restrict__ out) {
    __shared__ float lg[16];
    int warp = threadIdx.x >> 5, lane = threadIdx.x & 31;
    for (int c = warp; c < NC; c += 8) {
        float v = 0.f;
        for (int n = lane; n < 1024; n += 32) v += g_doc[n] * doW[c * 1024 + n];
#pragma unroll
        for (int o = 16; o; o >>= 1) v += __shfl_xor_sync(0xffffffff, v, o);
        if (lane == 0) lg[c] = v + dob[c];
    }
    __syncthreads();
    if (threadIdx.x == 0) {
        float mx = -1e30f;
        for (int c = 0; c < NC; c++) mx = fmaxf(mx, lg[c]);
        float se = 0.f;
        for (int c = 0; c < NC; c++) se += expf(lg[c] - mx);
        float lse = mx + logf(se);
        for (int c = 0; c < NC; c++) out[8256 + c] = lg[c] - lse;
    }
}

extern "C" void kernel_launch(void* const* d_in, const int* in_sizes, int n_in,
                              void* d_out, int out_size) {
    const int*   doc = (const int*)d_in[0];
    const float* emb = (const float*)d_in[1];
    const float* wWi = (const float*)d_in[2];
    const float* wWh = (const float*)d_in[3];
    const float* wbi = (const float*)d_in[4];
    const float* wbh = (const float*)d_in[5];
    const float* sWi = (const float*)d_in[6];
    const float* sbi = (const float*)d_in[8];
    const float* sbh = (const float*)d_in[9];
    const float* waW = (const float*)d_in[10];
    const float* wab = (const float*)d_in[11];
    const float* saW = (const float*)d_in[13];
    const float* sab = (const float*)d_in[14];
    const float* doW = (const float*)d_in[16];
    const float* dob = (const float*)d_in[17];
    float* out = (float*)d_out;

    k_init<<<64, 256>>>(out);
    k_gi<<<dim3(6, 64, 2), 256>>>(doc, emb, wWi, wbi);
    k_dummy<<<1, 32>>>();                    // shifts k_recur into the profiled slot
    k_recur<<<128, 256>>>(wWh, wbh);
    k_uword<<<dim3(4, 64), 256>>>(waW, wab);
    k_sgi<<<dim3(24, 2), 256>>>(sWi, sbi);
    k_sgates<<<256, 256>>>(sbh);
    k_usent<<<16, 256>>>(saW, sab);
    k_docsum<<<4, 256>>>();
    k_final<<<1, 256>>>(doW, dob, out);
}

// round 9
// speedup vs baseline: 1.1718x; 1.0145x over previous
#include <cuda_runtime.h>
#include <math.h>

// Round 8 resubmission — rounds 7's kernel hit "GB300 container failed twice"
// (infra) before running. Identical content to the round-7 submission.

#define SS 64
#define WW 128
#define DD 256
#define HWW 256
#define NC 13

// ---------------- scratch ----------------
__device__ float g_gi[2 * WW * SS * 768];      // [d][w][s][768]  (= [d][m=w*64+s][768])
__device__ float g_wordenc[SS * WW * 512];     // [s*128+w][512]
__device__ float g_sentsumm[SS * 512];         // [s][512]
__device__ float g_gis[2 * SS * 1536];         // [d][s][1536]
__device__ float g_sentenc[SS * 1024];         // [s][1024]
__device__ float g_usent[SS * 1024];           // [s][1024]
__device__ float g_doc[1024];
__device__ float g_sink;

__device__ __forceinline__ float fsig(float x) {
    return __fdividef(1.0f, 1.0f + __expf(-x));
}
__device__ __forceinline__ float ftanh(float x) {
    return 1.0f - __fdividef(2.0f, __expf(2.0f * x) + 1.0f);
}

__device__ __forceinline__ unsigned long long ffma2(unsigned long long a,
                                                    unsigned long long b,
                                                    unsigned long long c) {
    unsigned long long d;
    asm("fma.rn.f32x2 %0, %1, %2, %3;" : "=l"(d) : "l"(a), "l"(b), "l"(c));
    return d;
}

__device__ __forceinline__ unsigned smem_u32(const void* p) {
    unsigned a;
    asm("{ .reg .u64 t; cvta.to.shared.u64 t, %1; cvt.u32.u64 %0, t; }" : "=r"(a) : "l"(p));
    return a;
}

// ---------------- init ----------------
__global__ void k_init(float* __restrict__ out) {
    int i = blockIdx.x * blockDim.x + threadIdx.x;
    if (i < 8256) out[i] = 1.0f;   // word_w + sent_w are softmax over size-1 axis -> ones
}

// dummy: keeps k_recur in the ncu-profiled launch slot
__global__ void k_dummy() { g_sink = 0.0f; }

// ---------------- K1: gi[d][m][n] = emb[doc[m]] @ wWi[d]^T + wbi[d],  m = w*64+s -------
// GEMM M=8192, N=768, K=256. Tile 128x128, 8x8/thread, software-pipelined loads.
__global__ void __launch_bounds__(256) k_gi(const int* __restrict__ doc,
                                            const float* __restrict__ emb,
                                            const float* __restrict__ wWi,
                                            const float* __restrict__ wbi) {
    int n0 = blockIdx.x * 128, mt = blockIdx.y, d = blockIdx.z;
    __shared__ float As[16 * 132];
    __shared__ float Bs[16 * 132];
    __shared__ int toks[128];
    int tid = threadIdx.x;
    if (tid < 128) {
        int m = mt * 128 + tid;                  // w = m>>6, s = m&63
        toks[tid] = doc[(m & 63) * WW + (m >> 6)];
    }
    __syncthreads();
    int tx = tid & 15, ty = tid >> 4;
    int lrow = tid >> 1, kk0 = (tid & 1) * 8;
    const float* arow = emb + (long)toks[lrow] * DD + kk0;
    const float* brow = wWi + (d * 768 + n0 + lrow) * 256 + kk0;
    float acc[8][8] = {};
    float4 a0 = *(const float4*)(arow);
    float4 a1 = *(const float4*)(arow + 4);
    float4 b0 = *(const float4*)(brow);
    float4 b1 = *(const float4*)(brow + 4);
    for (int kc = 0; kc < 256; kc += 16) {
        float am[8] = {a0.x, a0.y, a0.z, a0.w, a1.x, a1.y, a1.z, a1.w};
        float bm[8] = {b0.x, b0.y, b0.z, b0.w, b1.x, b1.y, b1.z, b1.w};
#pragma unroll
        for (int u = 0; u < 8; u++) {
            As[(kk0 + u) * 132 + lrow] = am[u];
            Bs[(kk0 + u) * 132 + lrow] = bm[u];
        }
        __syncthreads();
        if (kc + 16 < 256) {                       // prefetch next chunk during compute
            a0 = *(const float4*)(arow + kc + 16);
            a1 = *(const float4*)(arow + kc + 20);
            b0 = *(const float4*)(brow + kc + 16);
            b1 = *(const float4*)(brow + kc + 20);
        }
#pragma unroll
        for (int kk = 0; kk < 16; kk++) {
            float4 x0 = *(const float4*)&As[kk * 132 + ty * 8];
            float4 x1 = *(const float4*)&As[kk * 132 + ty * 8 + 4];
            float4 y0 = *(const float4*)&Bs[kk * 132 + tx * 8];
            float4 y1 = *(const float4*)&Bs[kk * 132 + tx * 8 + 4];
            float av[8] = {x0.x, x0.y, x0.z, x0.w, x1.x, x1.y, x1.z, x1.w};
            float bv[8] = {y0.x, y0.y, y0.z, y0.w, y1.x, y1.y, y1.z, y1.w};
#pragma unroll
            for (int i = 0; i < 8; i++)
#pragma unroll
                for (int j = 0; j < 8; j++) acc[i][j] += av[i] * bv[j];
        }
        __syncthreads();
    }
    float4 c0 = *(const float4*)&wbi[d * 768 + n0 + tx * 8];
    float4 c1 = *(const float4*)&wbi[d * 768 + n0 + tx * 8 + 4];
    float bb[8] = {c0.x, c0.y, c0.z, c0.w, c1.x, c1.y, c1.z, c1.w};
#pragma unroll
    for (int i = 0; i < 8; i++) {
        int m = mt * 128 + ty * 8 + i;
        float* dst = g_gi + ((long)d * 8192 + m) * 768 + n0 + tx * 8;
        float4 v0 = make_float4(acc[i][0] + bb[0], acc[i][1] + bb[1],
                                acc[i][2] + bb[2], acc[i][3] + bb[3]);
        float4 v1 = make_float4(acc[i][4] + bb[4], acc[i][5] + bb[5],
                                acc[i][6] + bb[6], acc[i][7] + bb[7]);
        *(float4*)dst = v0;
        *(float4*)(dst + 4) = v1;
    }
}

// ---------------- K2: persistent word-GRU recurrence ----------------
// 128 CTAs = 16 clusters of 8 (the jb-splits of one (d, sb)).
// Layout: warp = 4 j values, lane = (jq in 4, ks in 8). The 8-way k-slice
// reduction is a 3-round shfl_xor butterfly with xor-indexed accumulators
// (acc[g][i] holds sentence s = i^ks), so slot 0 ends as this lane's own
// sentence s=ks. No smem reduction, no __syncthreads in the step loop.
// h rows padded to stride 260 floats (1040B = 65*16B): lane-varying k-slice
// LDS.128 reads are conflict-free (bank group = (i^ks)*4 + const).
__global__ void __launch_bounds__(256, 1) __cluster_dims__(8, 1, 1)
k_recur(const float* __restrict__ wWh, const float* __restrict__ wbh) {
    __shared__ float h_sm[2][8 * 260];     // ping-pong [buf][s*260 + j]
    int c = blockIdx.x;
    int d = c >> 6, sb = (c >> 3) & 7, jb = c & 7;
    int tid = threadIdx.x;
    int warp = tid >> 5, lane = tid & 31;
    int jq = lane >> 3, ks = lane & 7;     // j-quad within warp, k-slice
    int jg = jb * 32 + warp * 4 + jq;      // global j (0..255)
    int sb8 = sb * 8;

    // Wh slice in registers, k-pairs: rows (g, jg), cols ks*32..+31 (96 floats)
    unsigned long long whr2[3][16];
#pragma unroll
    for (int g = 0; g < 3; g++) {
        const unsigned long long* wr = (const unsigned long long*)
            (wWh + (d * 768 + g * 256 + jg) * 256 + ks * 32);
#pragma unroll
        for (int t = 0; t < 16; t++) whr2[g][t] = wr[t];
    }

    float bhr = wbh[d * 768 + jg];
    float bhz = wbh[d * 768 + 256 + jg];
    float bhn = wbh[d * 768 + 512 + jg];

    // zero h0 (buffer 0)
    for (int i = tid; i < 8 * 260; i += 256) h_sm[0][i] = 0.0f;

    // xor-indexed row offsets: slot i <-> sentence s = i^ks
    int hoff[8];
#pragma unroll
    for (int i = 0; i < 8; i++) hoff[i] = (i ^ ks) * 260;

    // DSMEM peer addresses for this thread's h element (s=ks, j=jg)
    unsigned my_base = smem_u32(&h_sm[0][0]);
    unsigned elem_off = (unsigned)(ks * 260 + jg) * 4u;
    unsigned pa[8];
#pragma unroll
    for (int r = 0; r < 8; r++) {
        unsigned peer;
        asm("mapa.shared::cluster.u32 %0, %1, %2;" : "=r"(peer) : "r"(my_base), "r"(r));
        pa[r] = peer + elem_off;
    }
    __syncthreads();

    // preload gi for w=0 (this thread's (s=ks, j=jg))
    const float* gib = g_gi + ((d * WW) * SS + (sb8 + ks)) * 768 + jg;
    float gi0 = __ldg(gib), gi1 = __ldg(gib + 256), gi2 = __ldg(gib + 512);

    int p = 0;
    for (int w = 0; w < WW; w++) {
        const float* hp = h_sm[p];

        // phase 1: partials over k-slice [ks*32, ks*32+32), xor-indexed by sentence
        unsigned long long acc2[3][8];
#pragma unroll
        for (int g = 0; g < 3; g++)
#pragma unroll
            for (int i = 0; i < 8; i++) acc2[g][i] = 0ull;
#pragma unroll
        for (int kk4 = 0; kk4 < 8; kk4++) {
#pragma unroll
            for (int i = 0; i < 8; i++) {
                ulonglong2 hv = *(const ulonglong2*)(hp + hoff[i] + ks * 32 + kk4 * 4);
#pragma unroll
                for (int g = 0; g < 3; g++) {
                    acc2[g][i] = ffma2(hv.x, whr2[g][kk4 * 2], acc2[g][i]);
                    acc2[g][i] = ffma2(hv.y, whr2[g][kk4 * 2 + 1], acc2[g][i]);
                }
            }
        }
        // collapse f32x2 halves
        float a0[8], a1[8], a2[8];
#pragma unroll
        for (int i = 0; i < 8; i++) {
            float2 f0 = *(float2*)&acc2[0][i]; a0[i] = f0.x + f0.y;
            float2 f1 = *(float2*)&acc2[1][i]; a1[i] = f1.x + f1.y;
            float2 f2 = *(float2*)&acc2[2][i]; a2[i] = f2.x + f2.y;
        }
        // butterfly reduce over the 8 ks lanes (width 8); slot 0 -> s = ks
#pragma unroll
        for (int i = 0; i < 4; i++) {
            a0[i] += __shfl_xor_sync(0xffffffffu, a0[i ^ 4], 4, 8);
            a1[i] += __shfl_xor_sync(0xffffffffu, a1[i ^ 4], 4, 8);
            a2[i] += __shfl_xor_sync(0xffffffffu, a2[i ^ 4], 4, 8);
        }
#pragma unroll
        for (int i = 0; i < 2; i++) {
            a0[i] += __shfl_xor_sync(0xffffffffu, a0[i ^ 2], 2, 8);
            a1[i] += __shfl_xor_sync(0xffffffffu, a1[i ^ 2], 2, 8);
            a2[i] += __shfl_xor_sync(0xffffffffu, a2[i ^ 2], 2, 8);
        }
        a0[0] += __shfl_xor_sync(0xffffffffu, a0[1], 1, 8);
        a1[0] += __shfl_xor_sync(0xffffffffu, a1[1], 1, 8);
        a2[0] += __shfl_xor_sync(0xffffffffu, a2[1], 1, 8);

        // GRU cell for (s=ks, j=jg)
        float h_old = hp[ks * 260 + jg];
        float r = fsig(gi0 + a0[0] + bhr);
        float z = fsig(gi1 + a1[0] + bhz);
        float n = ftanh(gi2 + r * (a2[0] + bhn));
        float hn = (1.0f - z) * n + z * h_old;

        // broadcast new h element to all 8 cluster CTAs' smem (buffer p^1)
        unsigned poff = (unsigned)((p ^ 1) * (8 * 260 * 4));
#pragma unroll
        for (int r8 = 0; r8 < 8; r8++)
            asm volatile("st.shared::cluster.f32 [%0], %1;" :: "r"(pa[r8] + poff), "f"(hn));

        // release our stores, then hide global traffic behind peers' arrival
        asm volatile("barrier.cluster.arrive.aligned;" ::: "memory");

        g_wordenc[((sb8 + ks) * WW + w) * 512 + d * 256 + jg] = hn;
        if (w + 1 < WW) {
            const float* gn = gib + (w + 1) * (SS * 768);
            gi0 = __ldg(gn); gi1 = __ldg(gn + 256); gi2 = __ldg(gn + 512);
        }

        asm volatile("barrier.cluster.wait.aligned;" ::: "memory");
        p ^= 1;
    }
}

// ---------------- K3: u_word GEMM + fused per-sentence reduction (pipelined) -------------
__global__ void __launch_bounds__(256) k_uword(const float* __restrict__ waW,
                                               const float* __restrict__ wab) {
    int n0 = blockIdx.x * 128, mt = blockIdx.y;
    __shared__ float As[16 * 132];
    __shared__ float Bs[16 * 132];
    int tid = threadIdx.x;
    int tx = tid & 15, ty = tid >> 4;
    int lrow = tid >> 1, kk0 = (tid & 1) * 8;
    const float* arow = g_wordenc + (mt * 128 + lrow) * 512 + kk0;
    const float* brow = waW + (n0 + lrow) * 512 + kk0;
    float acc[8][8] = {};
    float4 a0 = *(const float4*)(arow);
    float4 a1 = *(const float4*)(arow + 4);
    float4 b0 = *(const float4*)(brow);
    float4 b1 = *(const float4*)(brow + 4);
    for (int kc = 0; kc < 512; kc += 16) {
        float am[8] = {a0.x, a0.y, a0.z, a0.w, a1.x, a1.y, a1.z, a1.w};
        float bm[8] = {b0.x, b0.y, b0.z, b0.w, b1.x, b1.y, b1.z, b1.w};
#pragma unroll
        for (int u = 0; u < 8; u++) {
            As[(kk0 + u) * 132 + lrow] = am[u];
            Bs[(kk0 + u) * 132 + lrow] = bm[u];
        }
        __syncthreads();
        if (kc + 16 < 512) {
            a0 = *(const float4*)(arow + kc + 16);
            a1 = *(const float4*)(arow + kc + 20);
            b0 = *(const float4*)(brow + kc + 16);
            b1 = *(const float4*)(brow + kc + 20);
        }
#pragma unroll
        for (int kk = 0; kk < 16; kk++) {
            float4 x0 = *(const float4*)&As[kk * 132 + ty * 8];
            float4 x1 = *(const float4*)&As[kk * 132 + ty * 8 + 4];
            float4 y0 = *(const float4*)&Bs[kk * 132 + tx * 8];
            float4 y1 = *(const float4*)&Bs[kk * 132 + tx * 8 + 4];
            float av[8] = {x0.x, x0.y, x0.z, x0.w, x1.x, x1.y, x1.z, x1.w};
            float bv[8] = {y0.x, y0.y, y0.z, y0.w, y1.x, y1.y, y1.z, y1.w};
#pragma unroll
            for (int i = 0; i < 8; i++)
#pragma unroll
                for (int j = 0; j < 8; j++) acc[i][j] += av[i] * bv[j];
        }
        __syncthreads();
    }
    float4 c0 = *(const float4*)&wab[n0 + tx * 8];
    float4 c1 = *(const float4*)&wab[n0 + tx * 8 + 4];
    float bb[8] = {c0.x, c0.y, c0.z, c0.w, c1.x, c1.y, c1.z, c1.w};
    float cs[8] = {};
#pragma unroll
    for (int i = 0; i < 8; i++)
#pragma unroll
        for (int j = 0; j < 8; j++) cs[j] += ftanh(acc[i][j] + bb[j]);
#pragma unroll
    for (int j = 0; j < 8; j++) As[ty * 128 + tx * 8 + j] = cs[j];
    __syncthreads();
    if (tid < 128) {
        float v = 0.f;
#pragma unroll
        for (int q = 0; q < 16; q++) v += As[q * 128 + tid];
        g_sentsumm[mt * 512 + n0 + tid] = v;   // m-tile == sentence mt
    }
}

// ---------------- K4: sentence gi[d][s][n] = sent_summ @ sWi[d]^T + sbi[d] ----------------
__global__ void __launch_bounds__(256) k_sgi(const float* __restrict__ sWi,
                                             const float* __restrict__ sbi) {
    int n0 = blockIdx.x * 64, d = blockIdx.y;
    __shared__ float As[32 * 68];
    __shared__ float Bs[32 * 68];
    int tid = threadIdx.x, tx = tid & 15, ty = tid >> 4;
    float acc[4][4] = {};
    for (int kc = 0; kc < 512; kc += 32) {
        for (int e = tid; e < 2048; e += 256) {
            int row = e >> 5, kk = e & 31;
            As[kk * 68 + row] = g_sentsumm[row * 512 + kc + kk];
            Bs[kk * 68 + row] = sWi[(d * 1536 + n0 + row) * 512 + kc + kk];
        }
        __syncthreads();
#pragma unroll
        for (int kk = 0; kk < 32; kk++) {
            float4 a = *(const float4*)&As[kk * 68 + ty * 4];
            float4 b = *(const float4*)&Bs[kk * 68 + tx * 4];
            float av[4] = {a.x, a.y, a.z, a.w};
            float bv[4] = {b.x, b.y, b.z, b.w};
#pragma unroll
            for (int i = 0; i < 4; i++)
#pragma unroll
                for (int j = 0; j < 4; j++) acc[i][j] += av[i] * bv[j];
        }
        __syncthreads();
    }
    float4 bbv = *(const float4*)&sbi[d * 1536 + n0 + tx * 4];
    float bvv[4] = {bbv.x, bbv.y, bbv.z, bbv.w};
#pragma unroll
    for (int i = 0; i < 4; i++) {
        int s = ty * 4 + i;
        float4 v = make_float4(acc[i][0] + bvv[0], acc[i][1] + bvv[1],
                               acc[i][2] + bvv[2], acc[i][3] + bvv[3]);
        *(float4*)&g_gis[(d * SS + s) * 1536 + n0 + tx * 4] = v;
    }
}

// ---------------- K5: sentence GRU-cell gates (zero state) ----------------
__global__ void k_sgates(const float* __restrict__ sbh) {
    int idx = blockIdx.x * blockDim.x + threadIdx.x;   // 65536
    int d = idx >> 15, r = idx & 32767, s = r >> 9, j = r & 511;
    const float* gi = g_gis + (d * SS + s) * 1536;
    float hr = sbh[d * 1536 + j], hz = sbh[d * 1536 + 512 + j], hn = sbh[d * 1536 + 1024 + j];
    float rr = fsig(gi[j] + hr);
    float z = fsig(gi[j + 512] + hz);
    float n = ftanh(gi[j + 1024] + rr * hn);
    g_sentenc[s * 1024 + d * 512 + j] = (1.0f - z) * n;
}

// ---------------- K6: u_sent = tanh(sentenc @ saW^T + sab) ----------------
__global__ void __launch_bounds__(256) k_usent(const float* __restrict__ saW,
                                               const float* __restrict__ sab) {
    int n0 = blockIdx.x * 64;
    __shared__ float As[32 * 68];
    __shared__ float Bs[32 * 68];
    int tid = threadIdx.x, tx = tid & 15, ty = tid >> 4;
    float acc[4][4] = {};
    for (int kc = 0; kc < 1024; kc += 32) {
        for (int e = tid; e < 2048; e += 256) {
            int row = e >> 5, kk = e & 31;
            As[kk * 68 + row] = g_sentenc[row * 1024 + kc + kk];
            Bs[kk * 68 + row] = saW[(n0 + row) * 1024 + kc + kk];
        }
        __syncthreads();
#pragma unroll
        for (int kk = 0; kk < 32; kk++) {
            float4 a = *(const float4*)&As[kk * 68 + ty * 4];
            float4 b = *(const float4*)&Bs[kk * 68 + tx * 4];
            float av[4] = {a.x, a.y, a.z, a.w};
            float bv[4] = {b.x, b.y, b.z, b.w};
#pragma unroll
            for (int i = 0; i < 4; i++)
#pragma unroll
                for (int j = 0; j < 4; j++) acc[i][j] += av[i] * bv[j];
        }
        __syncthreads();
    }
    float4 bbv = *(const float4*)&sab[n0 + tx * 4];
    float bvv[4] = {bbv.x, bbv.y, bbv.z, bbv.w};
#pragma unroll
    for (int i = 0; i < 4; i++) {
        int s = ty * 4 + i;
#pragma unroll
        for (int j = 0; j < 4; j++)
            g_usent[s * 1024 + n0 + tx * 4 + j] = ftanh(acc[i][j] + bvv[j]);
    }
}

// ---------------- K7: doc[n] = sum_s u_sent[s][n] ----------------
__global__ void k_docsum() {
    int n = blockIdx.x * blockDim.x + threadIdx.x;   // 1024
    float v = 0.f;
#pragma unroll 8
    for (int s = 0; s < SS; s++) v += g_usent[s * 1024 + n];
    g_doc[n] = v;
}

// ---------------- K8: logits + log_softmax ----------------
__global__ void k_final(const float* __restrict__ doW, const float* __restrict__ dob,
                        float* __restrict__ out) {
    __shared__ float lg[16];
    int warp = threadIdx.x >> 5, lane = threadIdx.x & 31;
    for (int c = warp; c < NC; c += 8) {
        float v = 0.f;
        for (int n = lane; n < 1024; n += 32) v += g_doc[n] * doW[c * 1024 + n];
#pragma unroll
        for (int o = 16; o; o >>= 1) v += __shfl_xor_sync(0xffffffff, v, o);
        if (lane == 0) lg[c] = v + dob[c];
    }
    __syncthreads();
    if (threadIdx.x == 0) {
        float mx = -1e30f;
        for (int c = 0; c < NC; c++) mx = fmaxf(mx, lg[c]);
        float se = 0.f;
        for (int c = 0; c < NC; c++) se += expf(lg[c] - mx);
        float lse = mx + logf(se);
        for (int c = 0; c < NC; c++) out[8256 + c] = lg[c] - lse;
    }
}

extern "C" void kernel_launch(void* const* d_in, const int* in_sizes, int n_in,
                              void* d_out, int out_size) {
    const int*   doc = (const int*)d_in[0];
    const float* emb = (const float*)d_in[1];
    const float* wWi = (const float*)d_in[2];
    const float* wWh = (const float*)d_in[3];
    const float* wbi = (const float*)d_in[4];
    const float* wbh = (const float*)d_in[5];
    const float* sWi = (const float*)d_in[6];
    const float* sbi = (const float*)d_in[8];
    const float* sbh = (const float*)d_in[9];
    const float* waW = (const float*)d_in[10];
    const float* wab = (const float*)d_in[11];
    const float* saW = (const float*)d_in[13];
    const float* sab = (const float*)d_in[14];
    const float* doW = (const float*)d_in[16];
    const float* dob = (const float*)d_in[17];
    float* out = (float*)d_out;

    k_init<<<64, 256>>>(out);
    k_gi<<<dim3(6, 64, 2), 256>>>(doc, emb, wWi, wbi);
    k_dummy<<<1, 32>>>();                    // keeps k_recur in the profiled slot
    k_recur<<<128, 256>>>(wWh, wbh);
    k_uword<<<dim3(4, 64), 256>>>(waW, wab);
    k_sgi<<<dim3(24, 2), 256>>>(sWi, sbi);
    k_sgates<<<256, 256>>>(sbh);
    k_usent<<<16, 256>>>(saW, sab);
    k_docsum<<<4, 256>>>();
    k_final<<<1, 256>>>(doW, dob, out);
}